// round 3
// baseline (speedup 1.0000x reference)
#include <cuda_runtime.h>
#include <cuda_bf16.h>
#include <cstdint>

#define Nn 10000
#define Ee 320000

typedef unsigned long long ull;

// Scratch (allocation-free rule: __device__ globals)
__device__ float g_aggH[Nn * 256];
__device__ float g_aggC[Nn * 3];
__device__ float g_cnt[Nn];

// ---------------------------------------------------------------------------
// helpers
// ---------------------------------------------------------------------------
__device__ __forceinline__ ull pack_dup(float a) {
    ull r;
    asm("mov.b64 %0,{%1,%1};" : "=l"(r) : "f"(a));
    return r;
}
__device__ __forceinline__ float2 unpack2(ull v) {
    float2 r;
    asm("mov.b64 {%0,%1},%2;" : "=f"(r.x), "=f"(r.y) : "l"(v));
    return r;
}
__device__ __forceinline__ void fma2(ull& d, ull a, ull b) {
    asm("fma.rn.f32x2 %0,%1,%2,%0;" : "+l"(d) : "l"(a), "l"(b));
}
__device__ __forceinline__ float silu(float x) {
    return x / (1.0f + __expf(-x));
}

// One K-chunk (32) of the register-blocked GEMM.
// A: row-major, stride AS floats, rows r0..r0+3 used by this thread.
// B: [32][256] smem chunk. Thread owns cols {4*tx+64*jj+q}.
template <int AS>
__device__ __forceinline__ void mma_chunk(const float* __restrict__ A,
                                          const float* __restrict__ B,
                                          ull acc[4][8], int tx, int r0) {
#pragma unroll 8
    for (int k = 0; k < 32; k++) {
        ull ap[4];
#pragma unroll
        for (int r = 0; r < 4; r++) {
            float a = A[(r0 + r) * AS + k];
            ap[r] = pack_dup(a);
        }
        const float* brow = B + k * 256 + 4 * tx;
#pragma unroll
        for (int jj = 0; jj < 4; jj++) {
            ulonglong2 bv = *reinterpret_cast<const ulonglong2*>(brow + 64 * jj);
#pragma unroll
            for (int r = 0; r < 4; r++) {
                fma2(acc[r][2 * jj + 0], ap[r], bv.x);
                fma2(acc[r][2 * jj + 1], ap[r], bv.y);
            }
        }
    }
}

// ---------------------------------------------------------------------------
// zero scratch
// ---------------------------------------------------------------------------
__global__ void zero_kernel() {
    int idx = blockIdx.x * 256 + threadIdx.x;
    int stride = gridDim.x * 256;
    for (int i = idx; i < Nn * 256; i += stride) g_aggH[i] = 0.0f;
    for (int i = idx; i < Nn * 3; i += stride) g_aggC[i] = 0.0f;
    for (int i = idx; i < Nn; i += stride) g_cnt[i] = 0.0f;
}

// ---------------------------------------------------------------------------
// fused edge kernel: edge MLP + coord MLP + segment-sum atomics
// ---------------------------------------------------------------------------
struct __align__(16) ESm {
    float X[64 * 260];   // activation ping-pong buffer
    float B[32 * 256];   // weight chunk
    union {
        float A[64 * 33];  // gathered A chunk (GEMM1 only)
        float P[64 * 17];  // partial dot buffer (phase D only)
    };
    float w512[256];     // We1 row 512 (radial weight)
    float wc2[256];      // Wc2
    int   rowI[64];
    int   colI[64];
    float rad[64];
    float cd[64 * 3];
};

__global__ __launch_bounds__(256, 2) void edge_kernel(
    const float* __restrict__ h, const float* __restrict__ coord,
    const int* __restrict__ ei,
    const float* __restrict__ We1, const float* __restrict__ be1,
    const float* __restrict__ We2, const float* __restrict__ be2,
    const float* __restrict__ Wc1, const float* __restrict__ bc1,
    const float* __restrict__ Wc2, const float* __restrict__ bc2) {
    extern __shared__ char smem_raw[];
    ESm& s = *reinterpret_cast<ESm*>(smem_raw);

    const int tid = threadIdx.x;
    const int tx = tid & 15;
    const int ty = tid >> 4;
    const int r0 = ty * 4;
    const int eb = blockIdx.x * 64;

    if (tid < 64) {
        int e = eb + tid;
        int ri = ei[e];
        int ci = ei[Ee + e];
        s.rowI[tid] = ri;
        s.colI[tid] = ci;
        float dx = coord[ri * 3 + 0] - coord[ci * 3 + 0];
        float dy = coord[ri * 3 + 1] - coord[ci * 3 + 1];
        float dz = coord[ri * 3 + 2] - coord[ci * 3 + 2];
        s.cd[tid * 3 + 0] = dx;
        s.cd[tid * 3 + 1] = dy;
        s.cd[tid * 3 + 2] = dz;
        s.rad[tid] = dx * dx + dy * dy + dz * dz;
    }
    s.w512[tid] = We1[512 * 256 + tid];
    s.wc2[tid] = Wc2[tid];
    __syncthreads();

    ull acc[4][8];
#pragma unroll
    for (int r = 0; r < 4; r++)
#pragma unroll
        for (int j = 0; j < 8; j++) acc[r][j] = 0ULL;

    const int rr = tid >> 2;           // row this thread stages (0..63)
    const int kk = (tid & 3) * 8;      // 8-float span within the 32-chunk

    // ---------------- GEMM1: [h_i | h_j] @ We1[0:512], K = 512 ----------------
    for (int kc = 0; kc < 16; kc++) {
        const int kb = kc * 32;
        // stage A chunk (gather from h, L2-resident)
        {
            const float* src = (kc < 8)
                ? h + (size_t)s.rowI[rr] * 256 + kb + kk
                : h + (size_t)s.colI[rr] * 256 + (kb - 256) + kk;
            float4 v0 = *reinterpret_cast<const float4*>(src);
            float4 v1 = *reinterpret_cast<const float4*>(src + 4);
            float* da = &s.A[rr * 33 + kk];
            da[0] = v0.x; da[1] = v0.y; da[2] = v0.z; da[3] = v0.w;
            da[4] = v1.x; da[5] = v1.y; da[6] = v1.z; da[7] = v1.w;
        }
        // stage B chunk (We1 rows kb..kb+31, flat 8192-float copy)
        {
            const float4* wsrc = reinterpret_cast<const float4*>(We1 + (size_t)kb * 256);
            float4* wdst = reinterpret_cast<float4*>(s.B);
#pragma unroll
            for (int i = 0; i < 8; i++) wdst[tid + 256 * i] = wsrc[tid + 256 * i];
        }
        __syncthreads();
        mma_chunk<33>(&s.A[0], s.B, acc, tx, r0);
        __syncthreads();
    }

    // epilogue 1: + radial*We1[512] + be1, silu -> X
    {
        float rads[4];
#pragma unroll
        for (int r = 0; r < 4; r++) rads[r] = s.rad[r0 + r];
#pragma unroll
        for (int r = 0; r < 4; r++) {
#pragma unroll
            for (int jj = 0; jj < 4; jj++) {
                int c0 = 4 * tx + 64 * jj;
                float2 p0 = unpack2(acc[r][2 * jj + 0]);
                float2 p1 = unpack2(acc[r][2 * jj + 1]);
                float4 o;
                o.x = silu(p0.x + rads[r] * s.w512[c0 + 0] + __ldg(&be1[c0 + 0]));
                o.y = silu(p0.y + rads[r] * s.w512[c0 + 1] + __ldg(&be1[c0 + 1]));
                o.z = silu(p1.x + rads[r] * s.w512[c0 + 2] + __ldg(&be1[c0 + 2]));
                o.w = silu(p1.y + rads[r] * s.w512[c0 + 3] + __ldg(&be1[c0 + 3]));
                *reinterpret_cast<float4*>(&s.X[(r0 + r) * 260 + c0]) = o;
                acc[r][2 * jj + 0] = 0ULL;
                acc[r][2 * jj + 1] = 0ULL;
            }
        }
    }
    __syncthreads();

    // ---------------- GEMM2: out1 @ We2, K = 256 ----------------
    for (int kc = 0; kc < 8; kc++) {
        const int kb = kc * 32;
        const float4* wsrc = reinterpret_cast<const float4*>(We2 + (size_t)kb * 256);
        float4* wdst = reinterpret_cast<float4*>(s.B);
#pragma unroll
        for (int i = 0; i < 8; i++) wdst[tid + 256 * i] = wsrc[tid + 256 * i];
        __syncthreads();
        mma_chunk<260>(&s.X[kb], s.B, acc, tx, r0);
        __syncthreads();
    }

    // epilogue 2: silu -> edge_feat; atomic agg_h; overwrite X
    {
        int nr[4];
#pragma unroll
        for (int r = 0; r < 4; r++) nr[r] = s.rowI[r0 + r];
#pragma unroll
        for (int r = 0; r < 4; r++) {
#pragma unroll
            for (int jj = 0; jj < 4; jj++) {
                int c0 = 4 * tx + 64 * jj;
                float2 p0 = unpack2(acc[r][2 * jj + 0]);
                float2 p1 = unpack2(acc[r][2 * jj + 1]);
                float4 o;
                o.x = silu(p0.x + __ldg(&be2[c0 + 0]));
                o.y = silu(p0.y + __ldg(&be2[c0 + 1]));
                o.z = silu(p1.x + __ldg(&be2[c0 + 2]));
                o.w = silu(p1.y + __ldg(&be2[c0 + 3]));
                float* gh = &g_aggH[(size_t)nr[r] * 256 + c0];
                atomicAdd(gh + 0, o.x);
                atomicAdd(gh + 1, o.y);
                atomicAdd(gh + 2, o.z);
                atomicAdd(gh + 3, o.w);
                *reinterpret_cast<float4*>(&s.X[(r0 + r) * 260 + c0]) = o;
                acc[r][2 * jj + 0] = 0ULL;
                acc[r][2 * jj + 1] = 0ULL;
            }
        }
    }
    __syncthreads();

    // ---------------- GEMM3: edge_feat @ Wc1, K = 256 ----------------
    for (int kc = 0; kc < 8; kc++) {
        const int kb = kc * 32;
        const float4* wsrc = reinterpret_cast<const float4*>(Wc1 + (size_t)kb * 256);
        float4* wdst = reinterpret_cast<float4*>(s.B);
#pragma unroll
        for (int i = 0; i < 8; i++) wdst[tid + 256 * i] = wsrc[tid + 256 * i];
        __syncthreads();
        mma_chunk<260>(&s.X[kb], s.B, acc, tx, r0);
        __syncthreads();
    }

    // epilogue 3: silu, partial dot with Wc2
    {
        float part[4] = {0.f, 0.f, 0.f, 0.f};
#pragma unroll
        for (int r = 0; r < 4; r++) {
#pragma unroll
            for (int jj = 0; jj < 4; jj++) {
                int c0 = 4 * tx + 64 * jj;
                float2 p0 = unpack2(acc[r][2 * jj + 0]);
                float2 p1 = unpack2(acc[r][2 * jj + 1]);
                float c_0 = silu(p0.x + __ldg(&bc1[c0 + 0]));
                float c_1 = silu(p0.y + __ldg(&bc1[c0 + 1]));
                float c_2 = silu(p1.x + __ldg(&bc1[c0 + 2]));
                float c_3 = silu(p1.y + __ldg(&bc1[c0 + 3]));
                part[r] += c_0 * s.wc2[c0 + 0] + c_1 * s.wc2[c0 + 1] +
                           c_2 * s.wc2[c0 + 2] + c_3 * s.wc2[c0 + 3];
            }
        }
        __syncthreads();  // X reads done; P (union w/ A) safe to write
#pragma unroll
        for (int r = 0; r < 4; r++) s.P[(r0 + r) * 17 + tx] = part[r];
    }
    __syncthreads();

    if (tid < 64) {
        float sum = 0.f;
#pragma unroll
        for (int t = 0; t < 16; t++) sum += s.P[tid * 17 + t];
        float scal = sum + __ldg(bc2);
        int ri = s.rowI[tid];
        atomicAdd(&g_aggC[ri * 3 + 0], s.cd[tid * 3 + 0] * scal);
        atomicAdd(&g_aggC[ri * 3 + 1], s.cd[tid * 3 + 1] * scal);
        atomicAdd(&g_aggC[ri * 3 + 2], s.cd[tid * 3 + 2] * scal);
        atomicAdd(&g_cnt[ri], 1.0f);
    }
}

// ---------------------------------------------------------------------------
// node kernel: node MLP + coord epilogue
// ---------------------------------------------------------------------------
struct __align__(16) NSm {
    float X[64 * 260];
    float B[32 * 256];
    float A[64 * 33];
};

__global__ __launch_bounds__(256, 2) void node_kernel(
    const float* __restrict__ h, const float* __restrict__ coord,
    const float* __restrict__ Wn1, const float* __restrict__ bn1,
    const float* __restrict__ Wn2, const float* __restrict__ bn2,
    float* __restrict__ out) {
    extern __shared__ char smem_raw[];
    NSm& s = *reinterpret_cast<NSm*>(smem_raw);

    const int tid = threadIdx.x;
    const int tx = tid & 15;
    const int ty = tid >> 4;
    const int r0 = ty * 4;
    const int nb = blockIdx.x * 64;

    ull acc[4][8];
#pragma unroll
    for (int r = 0; r < 4; r++)
#pragma unroll
        for (int j = 0; j < 8; j++) acc[r][j] = 0ULL;

    const int rr = tid >> 2;
    const int kk = (tid & 3) * 8;
    const int nrow = nb + rr;
    const bool vA = nrow < Nn;

    // GEMM-N1: [h | agg_h] @ Wn1, K = 512
    for (int kc = 0; kc < 16; kc++) {
        const int kb = kc * 32;
        float4 v0 = make_float4(0.f, 0.f, 0.f, 0.f);
        float4 v1 = v0;
        if (vA) {
            const float* src = (kc < 8)
                ? h + (size_t)nrow * 256 + kb + kk
                : g_aggH + (size_t)nrow * 256 + (kb - 256) + kk;
            v0 = *reinterpret_cast<const float4*>(src);
            v1 = *reinterpret_cast<const float4*>(src + 4);
        }
        float* da = &s.A[rr * 33 + kk];
        da[0] = v0.x; da[1] = v0.y; da[2] = v0.z; da[3] = v0.w;
        da[4] = v1.x; da[5] = v1.y; da[6] = v1.z; da[7] = v1.w;

        const float4* wsrc = reinterpret_cast<const float4*>(Wn1 + (size_t)kb * 256);
        float4* wdst = reinterpret_cast<float4*>(s.B);
#pragma unroll
        for (int i = 0; i < 8; i++) wdst[tid + 256 * i] = wsrc[tid + 256 * i];
        __syncthreads();
        mma_chunk<33>(&s.A[0], s.B, acc, tx, r0);
        __syncthreads();
    }

    // epilogue: silu -> X
#pragma unroll
    for (int r = 0; r < 4; r++) {
#pragma unroll
        for (int jj = 0; jj < 4; jj++) {
            int c0 = 4 * tx + 64 * jj;
            float2 p0 = unpack2(acc[r][2 * jj + 0]);
            float2 p1 = unpack2(acc[r][2 * jj + 1]);
            float4 o;
            o.x = silu(p0.x + __ldg(&bn1[c0 + 0]));
            o.y = silu(p0.y + __ldg(&bn1[c0 + 1]));
            o.z = silu(p1.x + __ldg(&bn1[c0 + 2]));
            o.w = silu(p1.y + __ldg(&bn1[c0 + 3]));
            *reinterpret_cast<float4*>(&s.X[(r0 + r) * 260 + c0]) = o;
            acc[r][2 * jj + 0] = 0ULL;
            acc[r][2 * jj + 1] = 0ULL;
        }
    }
    __syncthreads();

    // GEMM-N2: @ Wn2, K = 256
    for (int kc = 0; kc < 8; kc++) {
        const int kb = kc * 32;
        const float4* wsrc = reinterpret_cast<const float4*>(Wn2 + (size_t)kb * 256);
        float4* wdst = reinterpret_cast<float4*>(s.B);
#pragma unroll
        for (int i = 0; i < 8; i++) wdst[tid + 256 * i] = wsrc[tid + 256 * i];
        __syncthreads();
        mma_chunk<260>(&s.X[kb], s.B, acc, tx, r0);
        __syncthreads();
    }

    // epilogue: + bn2 -> h_out
#pragma unroll
    for (int r = 0; r < 4; r++) {
        int n = nb + r0 + r;
        if (n < Nn) {
#pragma unroll
            for (int jj = 0; jj < 4; jj++) {
                int c0 = 4 * tx + 64 * jj;
                float2 p0 = unpack2(acc[r][2 * jj + 0]);
                float2 p1 = unpack2(acc[r][2 * jj + 1]);
                float4 o;
                o.x = p0.x + __ldg(&bn2[c0 + 0]);
                o.y = p0.y + __ldg(&bn2[c0 + 1]);
                o.z = p1.x + __ldg(&bn2[c0 + 2]);
                o.w = p1.y + __ldg(&bn2[c0 + 3]);
                *reinterpret_cast<float4*>(&out[(size_t)n * 256 + c0]) = o;
            }
        }
    }

    // coord epilogue
    if (tid < 64) {
        int n = nb + tid;
        if (n < Nn) {
            float cnt = fmaxf(g_cnt[n], 1.0f);
            float inv = 1.0f / cnt;
#pragma unroll
            for (int d = 0; d < 3; d++) {
                out[(size_t)Nn * 256 + n * 3 + d] =
                    coord[n * 3 + d] + g_aggC[n * 3 + d] * inv;
            }
        }
    }
}

// ---------------------------------------------------------------------------
extern "C" void kernel_launch(void* const* d_in, const int* in_sizes, int n_in,
                              void* d_out, int out_size) {
    const float* h     = (const float*)d_in[0];
    const float* coord = (const float*)d_in[1];
    const int*   ei    = (const int*)d_in[2];
    const float* We1   = (const float*)d_in[3];
    const float* be1   = (const float*)d_in[4];
    const float* We2   = (const float*)d_in[5];
    const float* be2   = (const float*)d_in[6];
    const float* Wn1   = (const float*)d_in[7];
    const float* bn1   = (const float*)d_in[8];
    const float* Wn2   = (const float*)d_in[9];
    const float* bn2   = (const float*)d_in[10];
    const float* Wc1   = (const float*)d_in[11];
    const float* bc1   = (const float*)d_in[12];
    const float* Wc2   = (const float*)d_in[13];
    const float* bc2   = (const float*)d_in[14];
    float* out = (float*)d_out;

    cudaFuncSetAttribute(edge_kernel, cudaFuncAttributeMaxDynamicSharedMemorySize,
                         (int)sizeof(ESm));
    cudaFuncSetAttribute(node_kernel, cudaFuncAttributeMaxDynamicSharedMemorySize,
                         (int)sizeof(NSm));

    zero_kernel<<<1280, 256>>>();
    edge_kernel<<<Ee / 64, 256, sizeof(ESm)>>>(h, coord, ei, We1, be1, We2, be2,
                                               Wc1, bc1, Wc2, bc2);
    node_kernel<<<(Nn + 63) / 64, 256, sizeof(NSm)>>>(h, coord, Wn1, bn1, Wn2, bn2,
                                                      out);
}

// round 4
// speedup vs baseline: 1.0007x; 1.0007x over previous
#include <cuda_runtime.h>
#include <cuda_bf16.h>
#include <cstdint>

#define Nn 10000
#define Ee 320000

typedef unsigned long long ull;

// Scratch (allocation-free rule: __device__ globals)
__device__ float g_aggH[Nn * 256];
__device__ float g_aggC[Nn * 3];
__device__ float g_cnt[Nn];

// ---------------------------------------------------------------------------
// helpers
// ---------------------------------------------------------------------------
__device__ __forceinline__ ull pack_dup(float a) {
    ull r;
    asm("mov.b64 %0,{%1,%1};" : "=l"(r) : "f"(a));
    return r;
}
__device__ __forceinline__ float2 unpack2(ull v) {
    float2 r;
    asm("mov.b64 {%0,%1},%2;" : "=f"(r.x), "=f"(r.y) : "l"(v));
    return r;
}
__device__ __forceinline__ void fma2(ull& d, ull a, ull b) {
    asm("fma.rn.f32x2 %0,%1,%2,%0;" : "+l"(d) : "l"(a), "l"(b));
}
__device__ __forceinline__ float silu(float x) {
    return x / (1.0f + __expf(-x));
}

// One K-chunk (32) of the register-blocked GEMM.
// A: row-major, stride AS floats, rows r0..r0+3 used by this thread.
// B: [32][256] smem chunk. Thread owns cols {4*tx+64*jj+q}.
template <int AS>
__device__ __forceinline__ void mma_chunk(const float* __restrict__ A,
                                          const float* __restrict__ B,
                                          ull acc[4][8], int tx, int r0) {
#pragma unroll 8
    for (int k = 0; k < 32; k++) {
        ull ap[4];
#pragma unroll
        for (int r = 0; r < 4; r++) {
            float a = A[(r0 + r) * AS + k];
            ap[r] = pack_dup(a);
        }
        const float* brow = B + k * 256 + 4 * tx;
#pragma unroll
        for (int jj = 0; jj < 4; jj++) {
            ulonglong2 bv = *reinterpret_cast<const ulonglong2*>(brow + 64 * jj);
#pragma unroll
            for (int r = 0; r < 4; r++) {
                fma2(acc[r][2 * jj + 0], ap[r], bv.x);
                fma2(acc[r][2 * jj + 1], ap[r], bv.y);
            }
        }
    }
}

// ---------------------------------------------------------------------------
// zero scratch
// ---------------------------------------------------------------------------
__global__ void zero_kernel() {
    int idx = blockIdx.x * 256 + threadIdx.x;
    int stride = gridDim.x * 256;
    for (int i = idx; i < Nn * 256; i += stride) g_aggH[i] = 0.0f;
    for (int i = idx; i < Nn * 3; i += stride) g_aggC[i] = 0.0f;
    for (int i = idx; i < Nn; i += stride) g_cnt[i] = 0.0f;
}

// ---------------------------------------------------------------------------
// fused edge kernel: edge MLP + coord MLP + segment-sum atomics
// ---------------------------------------------------------------------------
struct __align__(16) ESm {
    float X[64 * 260];   // activation ping-pong buffer
    float B[32 * 256];   // weight chunk
    union {
        float A[64 * 33];  // gathered A chunk (GEMM1 only)
        float P[64 * 17];  // partial dot buffer (phase D only)
    };
    float w512[256];     // We1 row 512 (radial weight)
    float wc2[256];      // Wc2
    int   rowI[64];
    int   colI[64];
    float rad[64];
    float cd[64 * 3];
};

__global__ __launch_bounds__(256, 2) void edge_kernel(
    const float* __restrict__ h, const float* __restrict__ coord,
    const int* __restrict__ ei,
    const float* __restrict__ We1, const float* __restrict__ be1,
    const float* __restrict__ We2, const float* __restrict__ be2,
    const float* __restrict__ Wc1, const float* __restrict__ bc1,
    const float* __restrict__ Wc2, const float* __restrict__ bc2) {
    extern __shared__ char smem_raw[];
    ESm& s = *reinterpret_cast<ESm*>(smem_raw);

    const int tid = threadIdx.x;
    const int tx = tid & 15;
    const int ty = tid >> 4;
    const int r0 = ty * 4;
    const int eb = blockIdx.x * 64;

    if (tid < 64) {
        int e = eb + tid;
        int ri = ei[e];
        int ci = ei[Ee + e];
        s.rowI[tid] = ri;
        s.colI[tid] = ci;
        float dx = coord[ri * 3 + 0] - coord[ci * 3 + 0];
        float dy = coord[ri * 3 + 1] - coord[ci * 3 + 1];
        float dz = coord[ri * 3 + 2] - coord[ci * 3 + 2];
        s.cd[tid * 3 + 0] = dx;
        s.cd[tid * 3 + 1] = dy;
        s.cd[tid * 3 + 2] = dz;
        s.rad[tid] = dx * dx + dy * dy + dz * dz;
    }
    s.w512[tid] = We1[512 * 256 + tid];
    s.wc2[tid] = Wc2[tid];
    __syncthreads();

    ull acc[4][8];
#pragma unroll
    for (int r = 0; r < 4; r++)
#pragma unroll
        for (int j = 0; j < 8; j++) acc[r][j] = 0ULL;

    const int rr = tid >> 2;           // row this thread stages (0..63)
    const int kk = (tid & 3) * 8;      // 8-float span within the 32-chunk

    // ---------------- GEMM1: [h_i | h_j] @ We1[0:512], K = 512 ----------------
    for (int kc = 0; kc < 16; kc++) {
        const int kb = kc * 32;
        // stage A chunk (gather from h, L2-resident)
        {
            const float* src = (kc < 8)
                ? h + (size_t)s.rowI[rr] * 256 + kb + kk
                : h + (size_t)s.colI[rr] * 256 + (kb - 256) + kk;
            float4 v0 = *reinterpret_cast<const float4*>(src);
            float4 v1 = *reinterpret_cast<const float4*>(src + 4);
            float* da = &s.A[rr * 33 + kk];
            da[0] = v0.x; da[1] = v0.y; da[2] = v0.z; da[3] = v0.w;
            da[4] = v1.x; da[5] = v1.y; da[6] = v1.z; da[7] = v1.w;
        }
        // stage B chunk (We1 rows kb..kb+31, flat 8192-float copy)
        {
            const float4* wsrc = reinterpret_cast<const float4*>(We1 + (size_t)kb * 256);
            float4* wdst = reinterpret_cast<float4*>(s.B);
#pragma unroll
            for (int i = 0; i < 8; i++) wdst[tid + 256 * i] = wsrc[tid + 256 * i];
        }
        __syncthreads();
        mma_chunk<33>(&s.A[0], s.B, acc, tx, r0);
        __syncthreads();
    }

    // epilogue 1: + radial*We1[512] + be1, silu -> X
    {
        float rads[4];
#pragma unroll
        for (int r = 0; r < 4; r++) rads[r] = s.rad[r0 + r];
#pragma unroll
        for (int r = 0; r < 4; r++) {
#pragma unroll
            for (int jj = 0; jj < 4; jj++) {
                int c0 = 4 * tx + 64 * jj;
                float2 p0 = unpack2(acc[r][2 * jj + 0]);
                float2 p1 = unpack2(acc[r][2 * jj + 1]);
                float4 o;
                o.x = silu(p0.x + rads[r] * s.w512[c0 + 0] + __ldg(&be1[c0 + 0]));
                o.y = silu(p0.y + rads[r] * s.w512[c0 + 1] + __ldg(&be1[c0 + 1]));
                o.z = silu(p1.x + rads[r] * s.w512[c0 + 2] + __ldg(&be1[c0 + 2]));
                o.w = silu(p1.y + rads[r] * s.w512[c0 + 3] + __ldg(&be1[c0 + 3]));
                *reinterpret_cast<float4*>(&s.X[(r0 + r) * 260 + c0]) = o;
                acc[r][2 * jj + 0] = 0ULL;
                acc[r][2 * jj + 1] = 0ULL;
            }
        }
    }
    __syncthreads();

    // ---------------- GEMM2: out1 @ We2, K = 256 ----------------
    for (int kc = 0; kc < 8; kc++) {
        const int kb = kc * 32;
        const float4* wsrc = reinterpret_cast<const float4*>(We2 + (size_t)kb * 256);
        float4* wdst = reinterpret_cast<float4*>(s.B);
#pragma unroll
        for (int i = 0; i < 8; i++) wdst[tid + 256 * i] = wsrc[tid + 256 * i];
        __syncthreads();
        mma_chunk<260>(&s.X[kb], s.B, acc, tx, r0);
        __syncthreads();
    }

    // epilogue 2: silu -> edge_feat; atomic agg_h; overwrite X
    {
        int nr[4];
#pragma unroll
        for (int r = 0; r < 4; r++) nr[r] = s.rowI[r0 + r];
#pragma unroll
        for (int r = 0; r < 4; r++) {
#pragma unroll
            for (int jj = 0; jj < 4; jj++) {
                int c0 = 4 * tx + 64 * jj;
                float2 p0 = unpack2(acc[r][2 * jj + 0]);
                float2 p1 = unpack2(acc[r][2 * jj + 1]);
                float4 o;
                o.x = silu(p0.x + __ldg(&be2[c0 + 0]));
                o.y = silu(p0.y + __ldg(&be2[c0 + 1]));
                o.z = silu(p1.x + __ldg(&be2[c0 + 2]));
                o.w = silu(p1.y + __ldg(&be2[c0 + 3]));
                float* gh = &g_aggH[(size_t)nr[r] * 256 + c0];
                atomicAdd(gh + 0, o.x);
                atomicAdd(gh + 1, o.y);
                atomicAdd(gh + 2, o.z);
                atomicAdd(gh + 3, o.w);
                *reinterpret_cast<float4*>(&s.X[(r0 + r) * 260 + c0]) = o;
                acc[r][2 * jj + 0] = 0ULL;
                acc[r][2 * jj + 1] = 0ULL;
            }
        }
    }
    __syncthreads();

    // ---------------- GEMM3: edge_feat @ Wc1, K = 256 ----------------
    for (int kc = 0; kc < 8; kc++) {
        const int kb = kc * 32;
        const float4* wsrc = reinterpret_cast<const float4*>(Wc1 + (size_t)kb * 256);
        float4* wdst = reinterpret_cast<float4*>(s.B);
#pragma unroll
        for (int i = 0; i < 8; i++) wdst[tid + 256 * i] = wsrc[tid + 256 * i];
        __syncthreads();
        mma_chunk<260>(&s.X[kb], s.B, acc, tx, r0);
        __syncthreads();
    }

    // epilogue 3: silu, partial dot with Wc2
    {
        float part[4] = {0.f, 0.f, 0.f, 0.f};
#pragma unroll
        for (int r = 0; r < 4; r++) {
#pragma unroll
            for (int jj = 0; jj < 4; jj++) {
                int c0 = 4 * tx + 64 * jj;
                float2 p0 = unpack2(acc[r][2 * jj + 0]);
                float2 p1 = unpack2(acc[r][2 * jj + 1]);
                float c_0 = silu(p0.x + __ldg(&bc1[c0 + 0]));
                float c_1 = silu(p0.y + __ldg(&bc1[c0 + 1]));
                float c_2 = silu(p1.x + __ldg(&bc1[c0 + 2]));
                float c_3 = silu(p1.y + __ldg(&bc1[c0 + 3]));
                part[r] += c_0 * s.wc2[c0 + 0] + c_1 * s.wc2[c0 + 1] +
                           c_2 * s.wc2[c0 + 2] + c_3 * s.wc2[c0 + 3];
            }
        }
        __syncthreads();  // X reads done; P (union w/ A) safe to write
#pragma unroll
        for (int r = 0; r < 4; r++) s.P[(r0 + r) * 17 + tx] = part[r];
    }
    __syncthreads();

    if (tid < 64) {
        float sum = 0.f;
#pragma unroll
        for (int t = 0; t < 16; t++) sum += s.P[tid * 17 + t];
        float scal = sum + __ldg(bc2);
        int ri = s.rowI[tid];
        atomicAdd(&g_aggC[ri * 3 + 0], s.cd[tid * 3 + 0] * scal);
        atomicAdd(&g_aggC[ri * 3 + 1], s.cd[tid * 3 + 1] * scal);
        atomicAdd(&g_aggC[ri * 3 + 2], s.cd[tid * 3 + 2] * scal);
        atomicAdd(&g_cnt[ri], 1.0f);
    }
}

// ---------------------------------------------------------------------------
// node kernel: node MLP + coord epilogue
// ---------------------------------------------------------------------------
struct __align__(16) NSm {
    float X[64 * 260];
    float B[32 * 256];
    float A[64 * 33];
};

__global__ __launch_bounds__(256, 2) void node_kernel(
    const float* __restrict__ h, const float* __restrict__ coord,
    const float* __restrict__ Wn1, const float* __restrict__ bn1,
    const float* __restrict__ Wn2, const float* __restrict__ bn2,
    float* __restrict__ out) {
    extern __shared__ char smem_raw[];
    NSm& s = *reinterpret_cast<NSm*>(smem_raw);

    const int tid = threadIdx.x;
    const int tx = tid & 15;
    const int ty = tid >> 4;
    const int r0 = ty * 4;
    const int nb = blockIdx.x * 64;

    ull acc[4][8];
#pragma unroll
    for (int r = 0; r < 4; r++)
#pragma unroll
        for (int j = 0; j < 8; j++) acc[r][j] = 0ULL;

    const int rr = tid >> 2;
    const int kk = (tid & 3) * 8;
    const int nrow = nb + rr;
    const bool vA = nrow < Nn;

    // GEMM-N1: [h | agg_h] @ Wn1, K = 512
    for (int kc = 0; kc < 16; kc++) {
        const int kb = kc * 32;
        float4 v0 = make_float4(0.f, 0.f, 0.f, 0.f);
        float4 v1 = v0;
        if (vA) {
            const float* src = (kc < 8)
                ? h + (size_t)nrow * 256 + kb + kk
                : g_aggH + (size_t)nrow * 256 + (kb - 256) + kk;
            v0 = *reinterpret_cast<const float4*>(src);
            v1 = *reinterpret_cast<const float4*>(src + 4);
        }
        float* da = &s.A[rr * 33 + kk];
        da[0] = v0.x; da[1] = v0.y; da[2] = v0.z; da[3] = v0.w;
        da[4] = v1.x; da[5] = v1.y; da[6] = v1.z; da[7] = v1.w;

        const float4* wsrc = reinterpret_cast<const float4*>(Wn1 + (size_t)kb * 256);
        float4* wdst = reinterpret_cast<float4*>(s.B);
#pragma unroll
        for (int i = 0; i < 8; i++) wdst[tid + 256 * i] = wsrc[tid + 256 * i];
        __syncthreads();
        mma_chunk<33>(&s.A[0], s.B, acc, tx, r0);
        __syncthreads();
    }

    // epilogue: silu -> X
#pragma unroll
    for (int r = 0; r < 4; r++) {
#pragma unroll
        for (int jj = 0; jj < 4; jj++) {
            int c0 = 4 * tx + 64 * jj;
            float2 p0 = unpack2(acc[r][2 * jj + 0]);
            float2 p1 = unpack2(acc[r][2 * jj + 1]);
            float4 o;
            o.x = silu(p0.x + __ldg(&bn1[c0 + 0]));
            o.y = silu(p0.y + __ldg(&bn1[c0 + 1]));
            o.z = silu(p1.x + __ldg(&bn1[c0 + 2]));
            o.w = silu(p1.y + __ldg(&bn1[c0 + 3]));
            *reinterpret_cast<float4*>(&s.X[(r0 + r) * 260 + c0]) = o;
            acc[r][2 * jj + 0] = 0ULL;
            acc[r][2 * jj + 1] = 0ULL;
        }
    }
    __syncthreads();

    // GEMM-N2: @ Wn2, K = 256
    for (int kc = 0; kc < 8; kc++) {
        const int kb = kc * 32;
        const float4* wsrc = reinterpret_cast<const float4*>(Wn2 + (size_t)kb * 256);
        float4* wdst = reinterpret_cast<float4*>(s.B);
#pragma unroll
        for (int i = 0; i < 8; i++) wdst[tid + 256 * i] = wsrc[tid + 256 * i];
        __syncthreads();
        mma_chunk<260>(&s.X[kb], s.B, acc, tx, r0);
        __syncthreads();
    }

    // epilogue: + bn2 -> h_out
#pragma unroll
    for (int r = 0; r < 4; r++) {
        int n = nb + r0 + r;
        if (n < Nn) {
#pragma unroll
            for (int jj = 0; jj < 4; jj++) {
                int c0 = 4 * tx + 64 * jj;
                float2 p0 = unpack2(acc[r][2 * jj + 0]);
                float2 p1 = unpack2(acc[r][2 * jj + 1]);
                float4 o;
                o.x = p0.x + __ldg(&bn2[c0 + 0]);
                o.y = p0.y + __ldg(&bn2[c0 + 1]);
                o.z = p1.x + __ldg(&bn2[c0 + 2]);
                o.w = p1.y + __ldg(&bn2[c0 + 3]);
                *reinterpret_cast<float4*>(&out[(size_t)n * 256 + c0]) = o;
            }
        }
    }

    // coord epilogue
    if (tid < 64) {
        int n = nb + tid;
        if (n < Nn) {
            float cnt = fmaxf(g_cnt[n], 1.0f);
            float inv = 1.0f / cnt;
#pragma unroll
            for (int d = 0; d < 3; d++) {
                out[(size_t)Nn * 256 + n * 3 + d] =
                    coord[n * 3 + d] + g_aggC[n * 3 + d] * inv;
            }
        }
    }
}

// ---------------------------------------------------------------------------
extern "C" void kernel_launch(void* const* d_in, const int* in_sizes, int n_in,
                              void* d_out, int out_size) {
    const float* h     = (const float*)d_in[0];
    const float* coord = (const float*)d_in[1];
    const int*   ei    = (const int*)d_in[2];
    const float* We1   = (const float*)d_in[3];
    const float* be1   = (const float*)d_in[4];
    const float* We2   = (const float*)d_in[5];
    const float* be2   = (const float*)d_in[6];
    const float* Wn1   = (const float*)d_in[7];
    const float* bn1   = (const float*)d_in[8];
    const float* Wn2   = (const float*)d_in[9];
    const float* bn2   = (const float*)d_in[10];
    const float* Wc1   = (const float*)d_in[11];
    const float* bc1   = (const float*)d_in[12];
    const float* Wc2   = (const float*)d_in[13];
    const float* bc2   = (const float*)d_in[14];
    float* out = (float*)d_out;

    cudaFuncSetAttribute(edge_kernel, cudaFuncAttributeMaxDynamicSharedMemorySize,
                         (int)sizeof(ESm));
    cudaFuncSetAttribute(node_kernel, cudaFuncAttributeMaxDynamicSharedMemorySize,
                         (int)sizeof(NSm));

    zero_kernel<<<1280, 256>>>();
    edge_kernel<<<Ee / 64, 256, sizeof(ESm)>>>(h, coord, ei, We1, be1, We2, be2,
                                               Wc1, bc1, Wc2, bc2);
    node_kernel<<<(Nn + 63) / 64, 256, sizeof(NSm)>>>(h, coord, Wn1, bn1, Wn2, bn2,
                                                      out);
}

// round 5
// speedup vs baseline: 1.0015x; 1.0008x over previous
#include <cuda_runtime.h>
#include <cuda_bf16.h>
#include <cstdint>

#define Nn 10000
#define Ee 320000

typedef unsigned long long ull;

// Scratch (allocation-free rule: __device__ globals)
__device__ float g_aggH[Nn * 256];
__device__ float g_aggC[Nn * 3];
__device__ float g_cnt[Nn];

// ---------------------------------------------------------------------------
// helpers
// ---------------------------------------------------------------------------
__device__ __forceinline__ ull pack_dup(float a) {
    ull r;
    asm("mov.b64 %0,{%1,%1};" : "=l"(r) : "f"(a));
    return r;
}
__device__ __forceinline__ float2 unpack2(ull v) {
    float2 r;
    asm("mov.b64 {%0,%1},%2;" : "=f"(r.x), "=f"(r.y) : "l"(v));
    return r;
}
__device__ __forceinline__ void fma2(ull& d, ull a, ull b) {
    asm("fma.rn.f32x2 %0,%1,%2,%0;" : "+l"(d) : "l"(a), "l"(b));
}
__device__ __forceinline__ float silu(float x) {
    return x / (1.0f + __expf(-x));
}

// One K-chunk (32) of the register-blocked GEMM.
// A: row-major, stride AS floats, rows r0..r0+3 used by this thread.
// B: [32][256] smem chunk. Thread owns cols {4*tx+64*jj+q}.
template <int AS>
__device__ __forceinline__ void mma_chunk(const float* __restrict__ A,
                                          const float* __restrict__ B,
                                          ull acc[4][8], int tx, int r0) {
#pragma unroll 8
    for (int k = 0; k < 32; k++) {
        ull ap[4];
#pragma unroll
        for (int r = 0; r < 4; r++) {
            float a = A[(r0 + r) * AS + k];
            ap[r] = pack_dup(a);
        }
        const float* brow = B + k * 256 + 4 * tx;
#pragma unroll
        for (int jj = 0; jj < 4; jj++) {
            ulonglong2 bv = *reinterpret_cast<const ulonglong2*>(brow + 64 * jj);
#pragma unroll
            for (int r = 0; r < 4; r++) {
                fma2(acc[r][2 * jj + 0], ap[r], bv.x);
                fma2(acc[r][2 * jj + 1], ap[r], bv.y);
            }
        }
    }
}

// ---------------------------------------------------------------------------
// zero scratch
// ---------------------------------------------------------------------------
__global__ void zero_kernel() {
    int idx = blockIdx.x * 256 + threadIdx.x;
    int stride = gridDim.x * 256;
    for (int i = idx; i < Nn * 256; i += stride) g_aggH[i] = 0.0f;
    for (int i = idx; i < Nn * 3; i += stride) g_aggC[i] = 0.0f;
    for (int i = idx; i < Nn; i += stride) g_cnt[i] = 0.0f;
}

// ---------------------------------------------------------------------------
// fused edge kernel: edge MLP + coord MLP + segment-sum atomics
// ---------------------------------------------------------------------------
struct __align__(16) ESm {
    float X[64 * 260];   // activation ping-pong buffer
    float B[32 * 256];   // weight chunk
    union {
        float A[64 * 33];  // gathered A chunk (GEMM1 only)
        float P[64 * 17];  // partial dot buffer (phase D only)
    };
    float w512[256];     // We1 row 512 (radial weight)
    float wc2[256];      // Wc2
    int   rowI[64];
    int   colI[64];
    float rad[64];
    float cd[64 * 3];
};

__global__ __launch_bounds__(256, 2) void edge_kernel(
    const float* __restrict__ h, const float* __restrict__ coord,
    const int* __restrict__ ei,
    const float* __restrict__ We1, const float* __restrict__ be1,
    const float* __restrict__ We2, const float* __restrict__ be2,
    const float* __restrict__ Wc1, const float* __restrict__ bc1,
    const float* __restrict__ Wc2, const float* __restrict__ bc2) {
    extern __shared__ char smem_raw[];
    ESm& s = *reinterpret_cast<ESm*>(smem_raw);

    const int tid = threadIdx.x;
    const int tx = tid & 15;
    const int ty = tid >> 4;
    const int r0 = ty * 4;
    const int eb = blockIdx.x * 64;

    if (tid < 64) {
        int e = eb + tid;
        int ri = ei[e];
        int ci = ei[Ee + e];
        s.rowI[tid] = ri;
        s.colI[tid] = ci;
        float dx = coord[ri * 3 + 0] - coord[ci * 3 + 0];
        float dy = coord[ri * 3 + 1] - coord[ci * 3 + 1];
        float dz = coord[ri * 3 + 2] - coord[ci * 3 + 2];
        s.cd[tid * 3 + 0] = dx;
        s.cd[tid * 3 + 1] = dy;
        s.cd[tid * 3 + 2] = dz;
        s.rad[tid] = dx * dx + dy * dy + dz * dz;
    }
    s.w512[tid] = We1[512 * 256 + tid];
    s.wc2[tid] = Wc2[tid];
    __syncthreads();

    ull acc[4][8];
#pragma unroll
    for (int r = 0; r < 4; r++)
#pragma unroll
        for (int j = 0; j < 8; j++) acc[r][j] = 0ULL;

    const int rr = tid >> 2;           // row this thread stages (0..63)
    const int kk = (tid & 3) * 8;      // 8-float span within the 32-chunk

    // ---------------- GEMM1: [h_i | h_j] @ We1[0:512], K = 512 ----------------
    for (int kc = 0; kc < 16; kc++) {
        const int kb = kc * 32;
        // stage A chunk (gather from h, L2-resident)
        {
            const float* src = (kc < 8)
                ? h + (size_t)s.rowI[rr] * 256 + kb + kk
                : h + (size_t)s.colI[rr] * 256 + (kb - 256) + kk;
            float4 v0 = *reinterpret_cast<const float4*>(src);
            float4 v1 = *reinterpret_cast<const float4*>(src + 4);
            float* da = &s.A[rr * 33 + kk];
            da[0] = v0.x; da[1] = v0.y; da[2] = v0.z; da[3] = v0.w;
            da[4] = v1.x; da[5] = v1.y; da[6] = v1.z; da[7] = v1.w;
        }
        // stage B chunk (We1 rows kb..kb+31, flat 8192-float copy)
        {
            const float4* wsrc = reinterpret_cast<const float4*>(We1 + (size_t)kb * 256);
            float4* wdst = reinterpret_cast<float4*>(s.B);
#pragma unroll
            for (int i = 0; i < 8; i++) wdst[tid + 256 * i] = wsrc[tid + 256 * i];
        }
        __syncthreads();
        mma_chunk<33>(&s.A[0], s.B, acc, tx, r0);
        __syncthreads();
    }

    // epilogue 1: + radial*We1[512] + be1, silu -> X
    {
        float rads[4];
#pragma unroll
        for (int r = 0; r < 4; r++) rads[r] = s.rad[r0 + r];
#pragma unroll
        for (int r = 0; r < 4; r++) {
#pragma unroll
            for (int jj = 0; jj < 4; jj++) {
                int c0 = 4 * tx + 64 * jj;
                float2 p0 = unpack2(acc[r][2 * jj + 0]);
                float2 p1 = unpack2(acc[r][2 * jj + 1]);
                float4 o;
                o.x = silu(p0.x + rads[r] * s.w512[c0 + 0] + __ldg(&be1[c0 + 0]));
                o.y = silu(p0.y + rads[r] * s.w512[c0 + 1] + __ldg(&be1[c0 + 1]));
                o.z = silu(p1.x + rads[r] * s.w512[c0 + 2] + __ldg(&be1[c0 + 2]));
                o.w = silu(p1.y + rads[r] * s.w512[c0 + 3] + __ldg(&be1[c0 + 3]));
                *reinterpret_cast<float4*>(&s.X[(r0 + r) * 260 + c0]) = o;
                acc[r][2 * jj + 0] = 0ULL;
                acc[r][2 * jj + 1] = 0ULL;
            }
        }
    }
    __syncthreads();

    // ---------------- GEMM2: out1 @ We2, K = 256 ----------------
    for (int kc = 0; kc < 8; kc++) {
        const int kb = kc * 32;
        const float4* wsrc = reinterpret_cast<const float4*>(We2 + (size_t)kb * 256);
        float4* wdst = reinterpret_cast<float4*>(s.B);
#pragma unroll
        for (int i = 0; i < 8; i++) wdst[tid + 256 * i] = wsrc[tid + 256 * i];
        __syncthreads();
        mma_chunk<260>(&s.X[kb], s.B, acc, tx, r0);
        __syncthreads();
    }

    // epilogue 2: silu -> edge_feat; atomic agg_h; overwrite X
    {
        int nr[4];
#pragma unroll
        for (int r = 0; r < 4; r++) nr[r] = s.rowI[r0 + r];
#pragma unroll
        for (int r = 0; r < 4; r++) {
#pragma unroll
            for (int jj = 0; jj < 4; jj++) {
                int c0 = 4 * tx + 64 * jj;
                float2 p0 = unpack2(acc[r][2 * jj + 0]);
                float2 p1 = unpack2(acc[r][2 * jj + 1]);
                float4 o;
                o.x = silu(p0.x + __ldg(&be2[c0 + 0]));
                o.y = silu(p0.y + __ldg(&be2[c0 + 1]));
                o.z = silu(p1.x + __ldg(&be2[c0 + 2]));
                o.w = silu(p1.y + __ldg(&be2[c0 + 3]));
                float* gh = &g_aggH[(size_t)nr[r] * 256 + c0];
                atomicAdd(gh + 0, o.x);
                atomicAdd(gh + 1, o.y);
                atomicAdd(gh + 2, o.z);
                atomicAdd(gh + 3, o.w);
                *reinterpret_cast<float4*>(&s.X[(r0 + r) * 260 + c0]) = o;
                acc[r][2 * jj + 0] = 0ULL;
                acc[r][2 * jj + 1] = 0ULL;
            }
        }
    }
    __syncthreads();

    // ---------------- GEMM3: edge_feat @ Wc1, K = 256 ----------------
    for (int kc = 0; kc < 8; kc++) {
        const int kb = kc * 32;
        const float4* wsrc = reinterpret_cast<const float4*>(Wc1 + (size_t)kb * 256);
        float4* wdst = reinterpret_cast<float4*>(s.B);
#pragma unroll
        for (int i = 0; i < 8; i++) wdst[tid + 256 * i] = wsrc[tid + 256 * i];
        __syncthreads();
        mma_chunk<260>(&s.X[kb], s.B, acc, tx, r0);
        __syncthreads();
    }

    // epilogue 3: silu, partial dot with Wc2
    {
        float part[4] = {0.f, 0.f, 0.f, 0.f};
#pragma unroll
        for (int r = 0; r < 4; r++) {
#pragma unroll
            for (int jj = 0; jj < 4; jj++) {
                int c0 = 4 * tx + 64 * jj;
                float2 p0 = unpack2(acc[r][2 * jj + 0]);
                float2 p1 = unpack2(acc[r][2 * jj + 1]);
                float c_0 = silu(p0.x + __ldg(&bc1[c0 + 0]));
                float c_1 = silu(p0.y + __ldg(&bc1[c0 + 1]));
                float c_2 = silu(p1.x + __ldg(&bc1[c0 + 2]));
                float c_3 = silu(p1.y + __ldg(&bc1[c0 + 3]));
                part[r] += c_0 * s.wc2[c0 + 0] + c_1 * s.wc2[c0 + 1] +
                           c_2 * s.wc2[c0 + 2] + c_3 * s.wc2[c0 + 3];
            }
        }
        __syncthreads();  // X reads done; P (union w/ A) safe to write
#pragma unroll
        for (int r = 0; r < 4; r++) s.P[(r0 + r) * 17 + tx] = part[r];
    }
    __syncthreads();

    if (tid < 64) {
        float sum = 0.f;
#pragma unroll
        for (int t = 0; t < 16; t++) sum += s.P[tid * 17 + t];
        float scal = sum + __ldg(bc2);
        int ri = s.rowI[tid];
        atomicAdd(&g_aggC[ri * 3 + 0], s.cd[tid * 3 + 0] * scal);
        atomicAdd(&g_aggC[ri * 3 + 1], s.cd[tid * 3 + 1] * scal);
        atomicAdd(&g_aggC[ri * 3 + 2], s.cd[tid * 3 + 2] * scal);
        atomicAdd(&g_cnt[ri], 1.0f);
    }
}

// ---------------------------------------------------------------------------
// node kernel: node MLP + coord epilogue
// ---------------------------------------------------------------------------
struct __align__(16) NSm {
    float X[64 * 260];
    float B[32 * 256];
    float A[64 * 33];
};

__global__ __launch_bounds__(256, 2) void node_kernel(
    const float* __restrict__ h, const float* __restrict__ coord,
    const float* __restrict__ Wn1, const float* __restrict__ bn1,
    const float* __restrict__ Wn2, const float* __restrict__ bn2,
    float* __restrict__ out) {
    extern __shared__ char smem_raw[];
    NSm& s = *reinterpret_cast<NSm*>(smem_raw);

    const int tid = threadIdx.x;
    const int tx = tid & 15;
    const int ty = tid >> 4;
    const int r0 = ty * 4;
    const int nb = blockIdx.x * 64;

    ull acc[4][8];
#pragma unroll
    for (int r = 0; r < 4; r++)
#pragma unroll
        for (int j = 0; j < 8; j++) acc[r][j] = 0ULL;

    const int rr = tid >> 2;
    const int kk = (tid & 3) * 8;
    const int nrow = nb + rr;
    const bool vA = nrow < Nn;

    // GEMM-N1: [h | agg_h] @ Wn1, K = 512
    for (int kc = 0; kc < 16; kc++) {
        const int kb = kc * 32;
        float4 v0 = make_float4(0.f, 0.f, 0.f, 0.f);
        float4 v1 = v0;
        if (vA) {
            const float* src = (kc < 8)
                ? h + (size_t)nrow * 256 + kb + kk
                : g_aggH + (size_t)nrow * 256 + (kb - 256) + kk;
            v0 = *reinterpret_cast<const float4*>(src);
            v1 = *reinterpret_cast<const float4*>(src + 4);
        }
        float* da = &s.A[rr * 33 + kk];
        da[0] = v0.x; da[1] = v0.y; da[2] = v0.z; da[3] = v0.w;
        da[4] = v1.x; da[5] = v1.y; da[6] = v1.z; da[7] = v1.w;

        const float4* wsrc = reinterpret_cast<const float4*>(Wn1 + (size_t)kb * 256);
        float4* wdst = reinterpret_cast<float4*>(s.B);
#pragma unroll
        for (int i = 0; i < 8; i++) wdst[tid + 256 * i] = wsrc[tid + 256 * i];
        __syncthreads();
        mma_chunk<33>(&s.A[0], s.B, acc, tx, r0);
        __syncthreads();
    }

    // epilogue: silu -> X
#pragma unroll
    for (int r = 0; r < 4; r++) {
#pragma unroll
        for (int jj = 0; jj < 4; jj++) {
            int c0 = 4 * tx + 64 * jj;
            float2 p0 = unpack2(acc[r][2 * jj + 0]);
            float2 p1 = unpack2(acc[r][2 * jj + 1]);
            float4 o;
            o.x = silu(p0.x + __ldg(&bn1[c0 + 0]));
            o.y = silu(p0.y + __ldg(&bn1[c0 + 1]));
            o.z = silu(p1.x + __ldg(&bn1[c0 + 2]));
            o.w = silu(p1.y + __ldg(&bn1[c0 + 3]));
            *reinterpret_cast<float4*>(&s.X[(r0 + r) * 260 + c0]) = o;
            acc[r][2 * jj + 0] = 0ULL;
            acc[r][2 * jj + 1] = 0ULL;
        }
    }
    __syncthreads();

    // GEMM-N2: @ Wn2, K = 256
    for (int kc = 0; kc < 8; kc++) {
        const int kb = kc * 32;
        const float4* wsrc = reinterpret_cast<const float4*>(Wn2 + (size_t)kb * 256);
        float4* wdst = reinterpret_cast<float4*>(s.B);
#pragma unroll
        for (int i = 0; i < 8; i++) wdst[tid + 256 * i] = wsrc[tid + 256 * i];
        __syncthreads();
        mma_chunk<260>(&s.X[kb], s.B, acc, tx, r0);
        __syncthreads();
    }

    // epilogue: + bn2 -> h_out
#pragma unroll
    for (int r = 0; r < 4; r++) {
        int n = nb + r0 + r;
        if (n < Nn) {
#pragma unroll
            for (int jj = 0; jj < 4; jj++) {
                int c0 = 4 * tx + 64 * jj;
                float2 p0 = unpack2(acc[r][2 * jj + 0]);
                float2 p1 = unpack2(acc[r][2 * jj + 1]);
                float4 o;
                o.x = p0.x + __ldg(&bn2[c0 + 0]);
                o.y = p0.y + __ldg(&bn2[c0 + 1]);
                o.z = p1.x + __ldg(&bn2[c0 + 2]);
                o.w = p1.y + __ldg(&bn2[c0 + 3]);
                *reinterpret_cast<float4*>(&out[(size_t)n * 256 + c0]) = o;
            }
        }
    }

    // coord epilogue
    if (tid < 64) {
        int n = nb + tid;
        if (n < Nn) {
            float cnt = fmaxf(g_cnt[n], 1.0f);
            float inv = 1.0f / cnt;
#pragma unroll
            for (int d = 0; d < 3; d++) {
                out[(size_t)Nn * 256 + n * 3 + d] =
                    coord[n * 3 + d] + g_aggC[n * 3 + d] * inv;
            }
        }
    }
}

// ---------------------------------------------------------------------------
extern "C" void kernel_launch(void* const* d_in, const int* in_sizes, int n_in,
                              void* d_out, int out_size) {
    const float* h     = (const float*)d_in[0];
    const float* coord = (const float*)d_in[1];
    const int*   ei    = (const int*)d_in[2];
    const float* We1   = (const float*)d_in[3];
    const float* be1   = (const float*)d_in[4];
    const float* We2   = (const float*)d_in[5];
    const float* be2   = (const float*)d_in[6];
    const float* Wn1   = (const float*)d_in[7];
    const float* bn1   = (const float*)d_in[8];
    const float* Wn2   = (const float*)d_in[9];
    const float* bn2   = (const float*)d_in[10];
    const float* Wc1   = (const float*)d_in[11];
    const float* bc1   = (const float*)d_in[12];
    const float* Wc2   = (const float*)d_in[13];
    const float* bc2   = (const float*)d_in[14];
    float* out = (float*)d_out;

    cudaFuncSetAttribute(edge_kernel, cudaFuncAttributeMaxDynamicSharedMemorySize,
                         (int)sizeof(ESm));
    cudaFuncSetAttribute(node_kernel, cudaFuncAttributeMaxDynamicSharedMemorySize,
                         (int)sizeof(NSm));

    zero_kernel<<<1280, 256>>>();
    edge_kernel<<<Ee / 64, 256, sizeof(ESm)>>>(h, coord, ei, We1, be1, We2, be2,
                                               Wc1, bc1, Wc2, bc2);
    node_kernel<<<(Nn + 63) / 64, 256, sizeof(NSm)>>>(h, coord, Wn1, bn1, Wn2, bn2,
                                                      out);
}

// round 7
// speedup vs baseline: 1.3554x; 1.3534x over previous
#include <cuda_runtime.h>
#include <cuda_fp16.h>
#include <cstdint>

#define Nn 10000
#define Ee 320000

typedef unsigned long long ull;
typedef unsigned int u32;

// ---------------- device scratch ----------------
__device__ float g_aggH[Nn * 256];
__device__ float g_aggC[Nn * 3];
__device__ float g_cnt[Nn];
__device__ __align__(16) __half g_hh[Nn * 256];
__device__ __align__(16) __half g_hl[Nn * 256];
__device__ __align__(16) __half g_W1h[256 * 512];
__device__ __align__(16) __half g_W1l[256 * 512];
__device__ __align__(16) __half g_W2h[256 * 256];
__device__ __align__(16) __half g_W2l[256 * 256];
__device__ __align__(16) __half g_Wch[256 * 256];
__device__ __align__(16) __half g_Wcl[256 * 256];

// ---------------- helpers ----------------
__device__ __forceinline__ u32 smem_u32(const void* p) {
    u32 a;
    asm("{ .reg .u64 t; cvta.to.shared.u64 t, %1; cvt.u32.u64 %0, t; }" : "=r"(a) : "l"(p));
    return a;
}
__device__ __forceinline__ void ldsm4(u32* r, u32 addr) {
    asm volatile("ldmatrix.sync.aligned.m8n8.x4.shared.b16 {%0,%1,%2,%3},[%4];"
                 : "=r"(r[0]), "=r"(r[1]), "=r"(r[2]), "=r"(r[3]) : "r"(addr));
}
__device__ __forceinline__ void mma16816(float* d, const u32* a, const u32* b) {
    asm volatile(
        "mma.sync.aligned.m16n8k16.row.col.f32.f16.f16.f32 "
        "{%0,%1,%2,%3},{%4,%5,%6,%7},{%8,%9},{%0,%1,%2,%3};"
        : "+f"(d[0]), "+f"(d[1]), "+f"(d[2]), "+f"(d[3])
        : "r"(a[0]), "r"(a[1]), "r"(a[2]), "r"(a[3]), "r"(b[0]), "r"(b[1]));
}
#define MMA6(d0p, d1p, ah, al, bh, bl)   \
    mma16816(d0p, ah, bh);               \
    mma16816(d0p, ah, bl);               \
    mma16816(d0p, al, bh);               \
    mma16816(d1p, ah, (bh) + 2);         \
    mma16816(d1p, ah, (bl) + 2);         \
    mma16816(d1p, al, (bh) + 2);

// MUFU-free silu (exp2 bit-splice + Newton reciprocal), rel err ~1e-6
__device__ __forceinline__ float silu_fast(float x) {
    float v = fmaxf(-fabsf(x) * 1.4426950408889634f, -30.0f);
    float r = v + 12582912.0f;
    int ni = __float_as_int(r) - 0x4B400000;
    float f = v - (r - 12582912.0f);
    float p = 1.3333558146e-3f;
    p = fmaf(p, f, 9.6181291076e-3f);
    p = fmaf(p, f, 5.5504108664e-2f);
    p = fmaf(p, f, 2.4015967802e-1f);
    p = fmaf(p, f, 6.9314718056e-1f);
    p = fmaf(p, f, 1.0f);
    float z = __int_as_float(__float_as_int(p) + (ni << 23));  // e^{-|x|}
    float d = 1.0f + z;
    float y = __int_as_float(0x7EF311C3 - __float_as_int(d));
    y = y * fmaf(-d, y, 2.0f);
    y = y * fmaf(-d, y, 2.0f);
    y = y * fmaf(-d, y, 2.0f);
    float sig = (x >= 0.0f) ? y : (1.0f - y);
    return x * sig;
}

// ---------------- prep kernels ----------------
__global__ void zero_kernel() {
    int idx = blockIdx.x * 256 + threadIdx.x, stride = gridDim.x * 256;
    for (int i = idx; i < Nn * 256; i += stride) g_aggH[i] = 0.0f;
    for (int i = idx; i < Nn * 3; i += stride) g_aggC[i] = 0.0f;
    for (int i = idx; i < Nn; i += stride) g_cnt[i] = 0.0f;
}
__global__ void prep_h(const float* __restrict__ h) {
    int i = blockIdx.x * 256 + threadIdx.x;
    if (i >= Nn * 256) return;
    float v = h[i];
    __half hb = __float2half_rn(v);
    g_hh[i] = hb;
    g_hl[i] = __float2half_rn(v - __half2float(hb));
}
// W [K][256] row-major -> W^T hi/lo [256][K]
__global__ void prep_w(const float* __restrict__ W, int K, int which) {
    __half *oh, *ol;
    if (which == 0)      { oh = g_W1h; ol = g_W1l; }
    else if (which == 1) { oh = g_W2h; ol = g_W2l; }
    else                 { oh = g_Wch; ol = g_Wcl; }
    int i = blockIdx.x * 256 + threadIdx.x;
    if (i >= K * 256) return;
    int k = i >> 8, n = i & 255;
    float v = W[i];
    __half hb = __float2half_rn(v);
    oh[(size_t)n * K + k] = hb;
    ol[(size_t)n * K + k] = __float2half_rn(v - __half2float(hb));
}

// ---------------- fused edge kernel ----------------
struct __align__(128) ESm {
    __half Xh[128 * 264];   // 67584 B
    __half Xl[128 * 264];   // 67584 B
    __half SB[40960];       // 81920 B staging union
    float w512[256], vbe1[256], vbe2[256], vbc1[256], vwc2[256];
    float rad[128], cd[384], P[256];
    int rowI[128], colI[128];
};

__device__ __forceinline__ void stpair(__half* X_h, __half* X_l, int r, int c, float o0, float o1) {
    __half h0 = __float2half_rn(o0), h1 = __float2half_rn(o1);
    __half l0 = __float2half_rn(o0 - __half2float(h0));
    __half l1 = __float2half_rn(o1 - __half2float(h1));
    *reinterpret_cast<__half2*>(&X_h[r * 264 + c]) = __halves2half2(h0, h1);
    *reinterpret_cast<__half2*>(&X_l[r * 264 + c]) = __halves2half2(l0, l1);
}

__global__ __launch_bounds__(256, 1) void edge_kernel(
    const float* __restrict__ coord, const int* __restrict__ ei,
    const float* __restrict__ We1, const float* __restrict__ be1,
    const float* __restrict__ be2, const float* __restrict__ bc1,
    const float* __restrict__ Wc2, const float* __restrict__ bc2) {
    extern __shared__ char smr[];
    ESm& s = *reinterpret_cast<ESm*>(smr);
    const int tid = threadIdx.x, wid = tid >> 5, lane = tid & 31;
    const int g = lane >> 2, tg = lane & 3;
    const int eb = blockIdx.x * 128;

    if (tid < 128) {
        int e = eb + tid;
        int ri = ei[e], ci = ei[Ee + e];
        s.rowI[tid] = ri; s.colI[tid] = ci;
        float dx = coord[ri * 3 + 0] - coord[ci * 3 + 0];
        float dy = coord[ri * 3 + 1] - coord[ci * 3 + 1];
        float dz = coord[ri * 3 + 2] - coord[ci * 3 + 2];
        s.cd[tid * 3 + 0] = dx; s.cd[tid * 3 + 1] = dy; s.cd[tid * 3 + 2] = dz;
        s.rad[tid] = dx * dx + dy * dy + dz * dz;
    }
    s.w512[tid] = We1[512 * 256 + tid];
    s.vbe1[tid] = be1[tid];
    s.vbe2[tid] = be2[tid];
    s.vbc1[tid] = bc1[tid];
    s.vwc2[tid] = Wc2[tid];
    __syncthreads();

    // staging carve
    __half* AH  = s.SB;
    __half* ALb = s.SB + 9216;
    __half* BH1 = s.SB + 18432;
    __half* BL1 = s.SB + 27648;
    __half* BH2 = s.SB;
    __half* BL2 = s.SB + 10240;

    // lane address components (ldmatrix)
    const int aRow = (lane & 7) + (lane & 8);
    const int aK8 = (lane & 16) ? 8 : 0;
    const int bRow = (lane & 7) + ((lane & 16) ? 8 : 0);
    const int bK8 = (lane & 8) ? 8 : 0;

    const u32 xh_b = smem_u32(s.Xh), xl_b = smem_u32(s.Xl);
    const int sr = tid >> 1, sh = tid & 1;

    float d[16][4];

    // ================= GEMM1: [h_i|h_j] @ We1^T (K=512), two N-passes =========
    const u32 a1h = smem_u32(AH) + ((u32)(wid * 16 + aRow) * 72 + aK8) * 2;
    const u32 a1l = smem_u32(ALb) + ((u32)(wid * 16 + aRow) * 72 + aK8) * 2;
    const u32 b1h = smem_u32(BH1) + ((u32)bRow * 72 + bK8) * 2;
    const u32 b1l = smem_u32(BL1) + ((u32)bRow * 72 + bK8) * 2;

    for (int p = 0; p < 2; p++) {
#pragma unroll
        for (int i = 0; i < 16; i++)
#pragma unroll
            for (int j = 0; j < 4; j++) d[i][j] = 0.0f;

        uint4 pa[8], pb[8];
        auto loadG1 = [&](int kc) {
            int idx = (kc < 4) ? s.rowI[sr] : s.colI[sr];
            int ko = (kc & 3) * 64 + sh * 32;
            const uint4* ah4 = (const uint4*)(g_hh + (size_t)idx * 256 + ko);
            const uint4* al4 = (const uint4*)(g_hl + (size_t)idx * 256 + ko);
            const uint4* bh4 = (const uint4*)(g_W1h + (size_t)(p * 128 + sr) * 512 + kc * 64 + sh * 32);
            const uint4* bl4 = (const uint4*)(g_W1l + (size_t)(p * 128 + sr) * 512 + kc * 64 + sh * 32);
#pragma unroll
            for (int j = 0; j < 4; j++) {
                pa[j] = ah4[j]; pa[4 + j] = al4[j];
                pb[j] = bh4[j]; pb[4 + j] = bl4[j];
            }
        };
        auto storeG1 = [&]() {
#pragma unroll
            for (int j = 0; j < 4; j++) {
                *(uint4*)&AH[sr * 72 + sh * 32 + j * 8]  = pa[j];
                *(uint4*)&ALb[sr * 72 + sh * 32 + j * 8] = pa[4 + j];
                *(uint4*)&BH1[sr * 72 + sh * 32 + j * 8] = pb[j];
                *(uint4*)&BL1[sr * 72 + sh * 32 + j * 8] = pb[4 + j];
            }
        };
        loadG1(0); storeG1(); __syncthreads();

        for (int kc = 0; kc < 8; kc++) {
            if (kc < 7) loadG1(kc + 1);
#pragma unroll
            for (int ks = 0; ks < 4; ks++) {
                u32 ah[4], al[4];
                ldsm4(ah, a1h + ks * 32);
                ldsm4(al, a1l + ks * 32);
#pragma unroll
                for (int ng = 0; ng < 8; ng++) {
                    u32 bh[4], bl[4];
                    ldsm4(bh, b1h + ng * 2304 + ks * 32);
                    ldsm4(bl, b1l + ng * 2304 + ks * 32);
                    MMA6(d[2 * ng], d[2 * ng + 1], ah, al, bh, bl);
                }
            }
            __syncthreads();
            if (kc < 7) { storeG1(); __syncthreads(); }
        }

        // epilogue 1
        {
            int r1 = wid * 16 + g, r2 = r1 + 8;
            float rad1 = s.rad[r1], rad2 = s.rad[r2];
#pragma unroll
            for (int ng = 0; ng < 8; ng++) {
#pragma unroll
                for (int hf = 0; hf < 2; hf++) {
                    int c = p * 128 + ng * 16 + hf * 8 + tg * 2;
                    float* dd = d[2 * ng + hf];
                    float o0 = silu_fast(dd[0] + rad1 * s.w512[c] + s.vbe1[c]);
                    float o1 = silu_fast(dd[1] + rad1 * s.w512[c + 1] + s.vbe1[c + 1]);
                    float o2 = silu_fast(dd[2] + rad2 * s.w512[c] + s.vbe1[c]);
                    float o3 = silu_fast(dd[3] + rad2 * s.w512[c + 1] + s.vbe1[c + 1]);
                    stpair(s.Xh, s.Xl, r1, c, o0, o1);
                    stpair(s.Xh, s.Xl, r2, c, o2, o3);
                }
            }
        }
        __syncthreads();
    }

    // ============ GEMM2 (We2) then GEMM3 (Wc1): K=256, two M-passes ==========
    const int mwid = wid & 3, nh = wid >> 2;
    for (int gm = 0; gm < 2; gm++) {
        const __half* Wh = gm ? g_Wch : g_W2h;
        const __half* Wl = gm ? g_Wcl : g_W2l;
        for (int mh = 0; mh < 2; mh++) {
#pragma unroll
            for (int i = 0; i < 16; i++)
#pragma unroll
                for (int j = 0; j < 4; j++) d[i][j] = 0.0f;

            const u32 aoff = ((u32)(mh * 64 + mwid * 16 + aRow) * 264 + aK8) * 2;
            const u32 b2h = smem_u32(BH2) + ((u32)(nh * 128 + bRow) * 40 + bK8) * 2;
            const u32 b2l = smem_u32(BL2) + ((u32)(nh * 128 + bRow) * 40 + bK8) * 2;

            uint4 pb2[8];
            auto loadG2 = [&](int kc) {
                const uint4* bh4 = (const uint4*)(Wh + (size_t)tid * 256 + kc * 32);
                const uint4* bl4 = (const uint4*)(Wl + (size_t)tid * 256 + kc * 32);
#pragma unroll
                for (int j = 0; j < 4; j++) { pb2[j] = bh4[j]; pb2[4 + j] = bl4[j]; }
            };
            auto storeG2 = [&]() {
#pragma unroll
                for (int j = 0; j < 4; j++) {
                    *(uint4*)&BH2[tid * 40 + j * 8] = pb2[j];
                    *(uint4*)&BL2[tid * 40 + j * 8] = pb2[4 + j];
                }
            };
            loadG2(0); storeG2(); __syncthreads();

            for (int kc = 0; kc < 8; kc++) {
                if (kc < 7) loadG2(kc + 1);
#pragma unroll
                for (int ks = 0; ks < 2; ks++) {
                    u32 ah[4], al[4];
                    ldsm4(ah, xh_b + aoff + (kc * 32 + ks * 16) * 2);
                    ldsm4(al, xl_b + aoff + (kc * 32 + ks * 16) * 2);
#pragma unroll
                    for (int ng = 0; ng < 8; ng++) {
                        u32 bh[4], bl[4];
                        ldsm4(bh, b2h + ng * 1280 + ks * 32);
                        ldsm4(bl, b2l + ng * 1280 + ks * 32);
                        MMA6(d[2 * ng], d[2 * ng + 1], ah, al, bh, bl);
                    }
                }
                __syncthreads();
                if (kc < 7) { storeG2(); __syncthreads(); }
            }

            int rr1 = mh * 64 + mwid * 16 + g, rr2 = rr1 + 8;
            if (gm == 0) {
                // epilogue 2: edge_feat = silu(D + be2); atomics to aggH; rewrite X
                int ri1 = s.rowI[rr1], ri2 = s.rowI[rr2];
#pragma unroll
                for (int ng = 0; ng < 8; ng++) {
#pragma unroll
                    for (int hf = 0; hf < 2; hf++) {
                        int c = nh * 128 + ng * 16 + hf * 8 + tg * 2;
                        float* dd = d[2 * ng + hf];
                        float o0 = silu_fast(dd[0] + s.vbe2[c]);
                        float o1 = silu_fast(dd[1] + s.vbe2[c + 1]);
                        float o2 = silu_fast(dd[2] + s.vbe2[c]);
                        float o3 = silu_fast(dd[3] + s.vbe2[c + 1]);
                        atomicAdd(&g_aggH[(size_t)ri1 * 256 + c], o0);
                        atomicAdd(&g_aggH[(size_t)ri1 * 256 + c + 1], o1);
                        atomicAdd(&g_aggH[(size_t)ri2 * 256 + c], o2);
                        atomicAdd(&g_aggH[(size_t)ri2 * 256 + c + 1], o3);
                        stpair(s.Xh, s.Xl, rr1, c, o0, o1);
                        stpair(s.Xh, s.Xl, rr2, c, o2, o3);
                    }
                }
            } else {
                // epilogue 3: partial dot(silu(D + bc1), wc2)
                float p1 = 0.0f, p2 = 0.0f;
#pragma unroll
                for (int ng = 0; ng < 8; ng++) {
#pragma unroll
                    for (int hf = 0; hf < 2; hf++) {
                        int c = nh * 128 + ng * 16 + hf * 8 + tg * 2;
                        float* dd = d[2 * ng + hf];
                        p1 = fmaf(silu_fast(dd[0] + s.vbc1[c]), s.vwc2[c], p1);
                        p1 = fmaf(silu_fast(dd[1] + s.vbc1[c + 1]), s.vwc2[c + 1], p1);
                        p2 = fmaf(silu_fast(dd[2] + s.vbc1[c]), s.vwc2[c], p2);
                        p2 = fmaf(silu_fast(dd[3] + s.vbc1[c + 1]), s.vwc2[c + 1], p2);
                    }
                }
                p1 += __shfl_xor_sync(0xFFFFFFFF, p1, 1);
                p1 += __shfl_xor_sync(0xFFFFFFFF, p1, 2);
                p2 += __shfl_xor_sync(0xFFFFFFFF, p2, 1);
                p2 += __shfl_xor_sync(0xFFFFFFFF, p2, 2);
                if (tg == 0) {
                    s.P[rr1 * 2 + nh] = p1;
                    s.P[rr2 * 2 + nh] = p2;
                }
            }
            __syncthreads();
        }
    }

    // coord atomics
    if (tid < 128) {
        float scal = s.P[tid * 2] + s.P[tid * 2 + 1] + __ldg(bc2);
        int ri = s.rowI[tid];
        atomicAdd(&g_aggC[ri * 3 + 0], s.cd[tid * 3 + 0] * scal);
        atomicAdd(&g_aggC[ri * 3 + 1], s.cd[tid * 3 + 1] * scal);
        atomicAdd(&g_aggC[ri * 3 + 2], s.cd[tid * 3 + 2] * scal);
        atomicAdd(&g_cnt[ri], 1.0f);
    }
}

// ---------------- node kernel (fp32 FFMA2, MUFU-free silu) ----------------
__device__ __forceinline__ ull pack_dup(float a) { ull r; asm("mov.b64 %0,{%1,%1};" : "=l"(r) : "f"(a)); return r; }
__device__ __forceinline__ float2 unpack2(ull v) { float2 r; asm("mov.b64 {%0,%1},%2;" : "=f"(r.x), "=f"(r.y) : "l"(v)); return r; }
__device__ __forceinline__ void fma2(ull& d, ull a, ull b) { asm("fma.rn.f32x2 %0,%1,%2,%0;" : "+l"(d) : "l"(a), "l"(b)); }

template <int AS>
__device__ __forceinline__ void mma_chunk(const float* __restrict__ A, const float* __restrict__ B,
                                          ull acc[4][8], int tx, int r0) {
#pragma unroll 8
    for (int k = 0; k < 32; k++) {
        ull ap[4];
#pragma unroll
        for (int r = 0; r < 4; r++) ap[r] = pack_dup(A[(r0 + r) * AS + k]);
        const float* brow = B + k * 256 + 4 * tx;
#pragma unroll
        for (int jj = 0; jj < 4; jj++) {
            ulonglong2 bv = *reinterpret_cast<const ulonglong2*>(brow + 64 * jj);
#pragma unroll
            for (int r = 0; r < 4; r++) { fma2(acc[r][2 * jj], ap[r], bv.x); fma2(acc[r][2 * jj + 1], ap[r], bv.y); }
        }
    }
}

struct __align__(16) NSm { float X[64 * 260]; float B[32 * 256]; float A[64 * 33]; };

__global__ __launch_bounds__(256, 2) void node_kernel(
    const float* __restrict__ h, const float* __restrict__ coord,
    const float* __restrict__ Wn1, const float* __restrict__ bn1,
    const float* __restrict__ Wn2, const float* __restrict__ bn2,
    float* __restrict__ out) {
    extern __shared__ char smem_raw[];
    NSm& s = *reinterpret_cast<NSm*>(smem_raw);
    const int tid = threadIdx.x, tx = tid & 15, ty = tid >> 4, r0 = ty * 4;
    const int nb = blockIdx.x * 64;
    ull acc[4][8];
#pragma unroll
    for (int r = 0; r < 4; r++)
#pragma unroll
        for (int j = 0; j < 8; j++) acc[r][j] = 0ULL;
    const int rr = tid >> 2, kk = (tid & 3) * 8;
    const int nrow = nb + rr;
    const bool vA = nrow < Nn;

    for (int kc = 0; kc < 16; kc++) {
        const int kb = kc * 32;
        float4 v0 = make_float4(0.f, 0.f, 0.f, 0.f), v1 = v0;
        if (vA) {
            const float* src = (kc < 8) ? h + (size_t)nrow * 256 + kb + kk
                                        : g_aggH + (size_t)nrow * 256 + (kb - 256) + kk;
            v0 = *reinterpret_cast<const float4*>(src);
            v1 = *reinterpret_cast<const float4*>(src + 4);
        }
        float* da = &s.A[rr * 33 + kk];
        da[0] = v0.x; da[1] = v0.y; da[2] = v0.z; da[3] = v0.w;
        da[4] = v1.x; da[5] = v1.y; da[6] = v1.z; da[7] = v1.w;
        const float4* wsrc = reinterpret_cast<const float4*>(Wn1 + (size_t)kb * 256);
        float4* wdst = reinterpret_cast<float4*>(s.B);
#pragma unroll
        for (int i = 0; i < 8; i++) wdst[tid + 256 * i] = wsrc[tid + 256 * i];
        __syncthreads();
        mma_chunk<33>(&s.A[0], s.B, acc, tx, r0);
        __syncthreads();
    }
#pragma unroll
    for (int r = 0; r < 4; r++)
#pragma unroll
        for (int jj = 0; jj < 4; jj++) {
            int c0 = 4 * tx + 64 * jj;
            float2 p0 = unpack2(acc[r][2 * jj]), p1 = unpack2(acc[r][2 * jj + 1]);
            float4 o;
            o.x = silu_fast(p0.x + __ldg(&bn1[c0 + 0]));
            o.y = silu_fast(p0.y + __ldg(&bn1[c0 + 1]));
            o.z = silu_fast(p1.x + __ldg(&bn1[c0 + 2]));
            o.w = silu_fast(p1.y + __ldg(&bn1[c0 + 3]));
            *reinterpret_cast<float4*>(&s.X[(r0 + r) * 260 + c0]) = o;
            acc[r][2 * jj] = 0ULL; acc[r][2 * jj + 1] = 0ULL;
        }
    __syncthreads();
    for (int kc = 0; kc < 8; kc++) {
        const int kb = kc * 32;
        const float4* wsrc = reinterpret_cast<const float4*>(Wn2 + (size_t)kb * 256);
        float4* wdst = reinterpret_cast<float4*>(s.B);
#pragma unroll
        for (int i = 0; i < 8; i++) wdst[tid + 256 * i] = wsrc[tid + 256 * i];
        __syncthreads();
        mma_chunk<260>(&s.X[kb], s.B, acc, tx, r0);
        __syncthreads();
    }
#pragma unroll
    for (int r = 0; r < 4; r++) {
        int n = nb + r0 + r;
        if (n < Nn) {
#pragma unroll
            for (int jj = 0; jj < 4; jj++) {
                int c0 = 4 * tx + 64 * jj;
                float2 p0 = unpack2(acc[r][2 * jj]), p1 = unpack2(acc[r][2 * jj + 1]);
                float4 o;
                o.x = p0.x + __ldg(&bn2[c0 + 0]); o.y = p0.y + __ldg(&bn2[c0 + 1]);
                o.z = p1.x + __ldg(&bn2[c0 + 2]); o.w = p1.y + __ldg(&bn2[c0 + 3]);
                *reinterpret_cast<float4*>(&out[(size_t)n * 256 + c0]) = o;
            }
        }
    }
    if (tid < 64) {
        int n = nb + tid;
        if (n < Nn) {
            float inv = 1.0f / fmaxf(g_cnt[n], 1.0f);
#pragma unroll
            for (int dd = 0; dd < 3; dd++)
                out[(size_t)Nn * 256 + n * 3 + dd] = coord[n * 3 + dd] + g_aggC[n * 3 + dd] * inv;
        }
    }
}

// ---------------------------------------------------------------------------
extern "C" void kernel_launch(void* const* d_in, const int* in_sizes, int n_in,
                              void* d_out, int out_size) {
    const float* h     = (const float*)d_in[0];
    const float* coord = (const float*)d_in[1];
    const int*   ei    = (const int*)d_in[2];
    const float* We1   = (const float*)d_in[3];
    const float* be1   = (const float*)d_in[4];
    const float* We2   = (const float*)d_in[5];
    const float* be2   = (const float*)d_in[6];
    const float* Wn1   = (const float*)d_in[7];
    const float* bn1   = (const float*)d_in[8];
    const float* Wn2   = (const float*)d_in[9];
    const float* bn2   = (const float*)d_in[10];
    const float* Wc1   = (const float*)d_in[11];
    const float* bc1   = (const float*)d_in[12];
    const float* Wc2   = (const float*)d_in[13];
    const float* bc2   = (const float*)d_in[14];
    float* out = (float*)d_out;

    cudaFuncSetAttribute(edge_kernel, cudaFuncAttributeMaxDynamicSharedMemorySize, (int)sizeof(ESm));
    cudaFuncSetAttribute(node_kernel, cudaFuncAttributeMaxDynamicSharedMemorySize, (int)sizeof(NSm));

    zero_kernel<<<1280, 256>>>();
    prep_h<<<(Nn * 256 + 255) / 256, 256>>>(h);
    prep_w<<<(512 * 256 + 255) / 256, 256>>>(We1, 512, 0);
    prep_w<<<(256 * 256 + 255) / 256, 256>>>(We2, 256, 1);
    prep_w<<<(256 * 256 + 255) / 256, 256>>>(Wc1, 256, 2);
    edge_kernel<<<Ee / 128, 256, sizeof(ESm)>>>(coord, ei, We1, be1, be2, bc1, Wc2, bc2);
    node_kernel<<<(Nn + 63) / 64, 256, sizeof(NSm)>>>(h, coord, Wn1, bn1, Wn2, bn2, out);
}

// round 8
// speedup vs baseline: 1.3562x; 1.0006x over previous
#include <cuda_runtime.h>
#include <cuda_fp16.h>
#include <cstdint>

#define Nn 10000
#define Ee 320000

typedef unsigned long long ull;
typedef unsigned int u32;

// ---------------- device scratch ----------------
__device__ float g_aggH[Nn * 256];
__device__ float g_aggC[Nn * 3];
__device__ float g_cnt[Nn];
__device__ __align__(16) __half g_hh[Nn * 256];
__device__ __align__(16) __half g_hl[Nn * 256];
__device__ __align__(16) __half g_W1h[256 * 512];
__device__ __align__(16) __half g_W1l[256 * 512];
__device__ __align__(16) __half g_W2h[256 * 256];
__device__ __align__(16) __half g_W2l[256 * 256];
__device__ __align__(16) __half g_Wch[256 * 256];
__device__ __align__(16) __half g_Wcl[256 * 256];

// ---------------- helpers ----------------
__device__ __forceinline__ u32 smem_u32(const void* p) {
    u32 a;
    asm("{ .reg .u64 t; cvta.to.shared.u64 t, %1; cvt.u32.u64 %0, t; }" : "=r"(a) : "l"(p));
    return a;
}
__device__ __forceinline__ void ldsm4(u32* r, u32 addr) {
    asm volatile("ldmatrix.sync.aligned.m8n8.x4.shared.b16 {%0,%1,%2,%3},[%4];"
                 : "=r"(r[0]), "=r"(r[1]), "=r"(r[2]), "=r"(r[3]) : "r"(addr));
}
__device__ __forceinline__ void mma16816(float* d, const u32* a, const u32* b) {
    asm volatile(
        "mma.sync.aligned.m16n8k16.row.col.f32.f16.f16.f32 "
        "{%0,%1,%2,%3},{%4,%5,%6,%7},{%8,%9},{%0,%1,%2,%3};"
        : "+f"(d[0]), "+f"(d[1]), "+f"(d[2]), "+f"(d[3])
        : "r"(a[0]), "r"(a[1]), "r"(a[2]), "r"(a[3]), "r"(b[0]), "r"(b[1]));
}
#define MMA6(d0p, d1p, ah, al, bh, bl)   \
    mma16816(d0p, ah, bh);               \
    mma16816(d0p, ah, bl);               \
    mma16816(d0p, al, bh);               \
    mma16816(d1p, ah, (bh) + 2);         \
    mma16816(d1p, ah, (bl) + 2);         \
    mma16816(d1p, al, (bh) + 2);

// MUFU-free silu (exp2 bit-splice + Newton reciprocal), rel err ~1e-6
__device__ __forceinline__ float silu_fast(float x) {
    float v = fmaxf(-fabsf(x) * 1.4426950408889634f, -30.0f);
    float r = v + 12582912.0f;
    int ni = __float_as_int(r) - 0x4B400000;
    float f = v - (r - 12582912.0f);
    float p = 1.3333558146e-3f;
    p = fmaf(p, f, 9.6181291076e-3f);
    p = fmaf(p, f, 5.5504108664e-2f);
    p = fmaf(p, f, 2.4015967802e-1f);
    p = fmaf(p, f, 6.9314718056e-1f);
    p = fmaf(p, f, 1.0f);
    float z = __int_as_float(__float_as_int(p) + (ni << 23));  // e^{-|x|}
    float d = 1.0f + z;
    float y = __int_as_float(0x7EF311C3 - __float_as_int(d));
    y = y * fmaf(-d, y, 2.0f);
    y = y * fmaf(-d, y, 2.0f);
    y = y * fmaf(-d, y, 2.0f);
    float sig = (x >= 0.0f) ? y : (1.0f - y);
    return x * sig;
}

// ---------------- prep kernels ----------------
__global__ void zero_kernel() {
    int idx = blockIdx.x * 256 + threadIdx.x, stride = gridDim.x * 256;
    for (int i = idx; i < Nn * 256; i += stride) g_aggH[i] = 0.0f;
    for (int i = idx; i < Nn * 3; i += stride) g_aggC[i] = 0.0f;
    for (int i = idx; i < Nn; i += stride) g_cnt[i] = 0.0f;
}
__global__ void prep_h(const float* __restrict__ h) {
    int i = blockIdx.x * 256 + threadIdx.x;
    if (i >= Nn * 256) return;
    float v = h[i];
    __half hb = __float2half_rn(v);
    g_hh[i] = hb;
    g_hl[i] = __float2half_rn(v - __half2float(hb));
}
// W [K][256] row-major -> W^T hi/lo [256][K]
__global__ void prep_w(const float* __restrict__ W, int K, int which) {
    __half *oh, *ol;
    if (which == 0)      { oh = g_W1h; ol = g_W1l; }
    else if (which == 1) { oh = g_W2h; ol = g_W2l; }
    else                 { oh = g_Wch; ol = g_Wcl; }
    int i = blockIdx.x * 256 + threadIdx.x;
    if (i >= K * 256) return;
    int k = i >> 8, n = i & 255;
    float v = W[i];
    __half hb = __float2half_rn(v);
    oh[(size_t)n * K + k] = hb;
    ol[(size_t)n * K + k] = __float2half_rn(v - __half2float(hb));
}

// ---------------- fused edge kernel ----------------
struct __align__(128) ESm {
    __half Xh[128 * 264];   // 67584 B
    __half Xl[128 * 264];   // 67584 B
    __half SB[40960];       // 81920 B staging union
    float w512[256], vbe1[256], vbe2[256], vbc1[256], vwc2[256];
    float rad[128], cd[384], P[256];
    int rowI[128], colI[128];
};

__device__ __forceinline__ void stpair(__half* X_h, __half* X_l, int r, int c, float o0, float o1) {
    __half h0 = __float2half_rn(o0), h1 = __float2half_rn(o1);
    __half l0 = __float2half_rn(o0 - __half2float(h0));
    __half l1 = __float2half_rn(o1 - __half2float(h1));
    *reinterpret_cast<__half2*>(&X_h[r * 264 + c]) = __halves2half2(h0, h1);
    *reinterpret_cast<__half2*>(&X_l[r * 264 + c]) = __halves2half2(l0, l1);
}

__global__ __launch_bounds__(256, 1) void edge_kernel(
    const float* __restrict__ coord, const int* __restrict__ ei,
    const float* __restrict__ We1, const float* __restrict__ be1,
    const float* __restrict__ be2, const float* __restrict__ bc1,
    const float* __restrict__ Wc2, const float* __restrict__ bc2) {
    extern __shared__ char smr[];
    ESm& s = *reinterpret_cast<ESm*>(smr);
    const int tid = threadIdx.x, wid = tid >> 5, lane = tid & 31;
    const int g = lane >> 2, tg = lane & 3;
    const int eb = blockIdx.x * 128;

    if (tid < 128) {
        int e = eb + tid;
        int ri = ei[e], ci = ei[Ee + e];
        s.rowI[tid] = ri; s.colI[tid] = ci;
        float dx = coord[ri * 3 + 0] - coord[ci * 3 + 0];
        float dy = coord[ri * 3 + 1] - coord[ci * 3 + 1];
        float dz = coord[ri * 3 + 2] - coord[ci * 3 + 2];
        s.cd[tid * 3 + 0] = dx; s.cd[tid * 3 + 1] = dy; s.cd[tid * 3 + 2] = dz;
        s.rad[tid] = dx * dx + dy * dy + dz * dz;
    }
    s.w512[tid] = We1[512 * 256 + tid];
    s.vbe1[tid] = be1[tid];
    s.vbe2[tid] = be2[tid];
    s.vbc1[tid] = bc1[tid];
    s.vwc2[tid] = Wc2[tid];
    __syncthreads();

    // staging carve
    __half* AH  = s.SB;
    __half* ALb = s.SB + 9216;
    __half* BH1 = s.SB + 18432;
    __half* BL1 = s.SB + 27648;
    __half* BH2 = s.SB;
    __half* BL2 = s.SB + 10240;

    // lane address components (ldmatrix)
    const int aRow = (lane & 7) + (lane & 8);
    const int aK8 = (lane & 16) ? 8 : 0;
    const int bRow = (lane & 7) + ((lane & 16) ? 8 : 0);
    const int bK8 = (lane & 8) ? 8 : 0;

    const u32 xh_b = smem_u32(s.Xh), xl_b = smem_u32(s.Xl);
    const int sr = tid >> 1, sh = tid & 1;

    float d[16][4];

    // ================= GEMM1: [h_i|h_j] @ We1^T (K=512), two N-passes =========
    const u32 a1h = smem_u32(AH) + ((u32)(wid * 16 + aRow) * 72 + aK8) * 2;
    const u32 a1l = smem_u32(ALb) + ((u32)(wid * 16 + aRow) * 72 + aK8) * 2;
    const u32 b1h = smem_u32(BH1) + ((u32)bRow * 72 + bK8) * 2;
    const u32 b1l = smem_u32(BL1) + ((u32)bRow * 72 + bK8) * 2;

    for (int p = 0; p < 2; p++) {
#pragma unroll
        for (int i = 0; i < 16; i++)
#pragma unroll
            for (int j = 0; j < 4; j++) d[i][j] = 0.0f;

        uint4 pa[8], pb[8];
        auto loadG1 = [&](int kc) {
            int idx = (kc < 4) ? s.rowI[sr] : s.colI[sr];
            int ko = (kc & 3) * 64 + sh * 32;
            const uint4* ah4 = (const uint4*)(g_hh + (size_t)idx * 256 + ko);
            const uint4* al4 = (const uint4*)(g_hl + (size_t)idx * 256 + ko);
            const uint4* bh4 = (const uint4*)(g_W1h + (size_t)(p * 128 + sr) * 512 + kc * 64 + sh * 32);
            const uint4* bl4 = (const uint4*)(g_W1l + (size_t)(p * 128 + sr) * 512 + kc * 64 + sh * 32);
#pragma unroll
            for (int j = 0; j < 4; j++) {
                pa[j] = ah4[j]; pa[4 + j] = al4[j];
                pb[j] = bh4[j]; pb[4 + j] = bl4[j];
            }
        };
        auto storeG1 = [&]() {
#pragma unroll
            for (int j = 0; j < 4; j++) {
                *(uint4*)&AH[sr * 72 + sh * 32 + j * 8]  = pa[j];
                *(uint4*)&ALb[sr * 72 + sh * 32 + j * 8] = pa[4 + j];
                *(uint4*)&BH1[sr * 72 + sh * 32 + j * 8] = pb[j];
                *(uint4*)&BL1[sr * 72 + sh * 32 + j * 8] = pb[4 + j];
            }
        };
        loadG1(0); storeG1(); __syncthreads();

        for (int kc = 0; kc < 8; kc++) {
            if (kc < 7) loadG1(kc + 1);
#pragma unroll
            for (int ks = 0; ks < 4; ks++) {
                u32 ah[4], al[4];
                ldsm4(ah, a1h + ks * 32);
                ldsm4(al, a1l + ks * 32);
#pragma unroll
                for (int ng = 0; ng < 8; ng++) {
                    u32 bh[4], bl[4];
                    ldsm4(bh, b1h + ng * 2304 + ks * 32);
                    ldsm4(bl, b1l + ng * 2304 + ks * 32);
                    MMA6(d[2 * ng], d[2 * ng + 1], ah, al, bh, bl);
                }
            }
            __syncthreads();
            if (kc < 7) { storeG1(); __syncthreads(); }
        }

        // epilogue 1
        {
            int r1 = wid * 16 + g, r2 = r1 + 8;
            float rad1 = s.rad[r1], rad2 = s.rad[r2];
#pragma unroll
            for (int ng = 0; ng < 8; ng++) {
#pragma unroll
                for (int hf = 0; hf < 2; hf++) {
                    int c = p * 128 + ng * 16 + hf * 8 + tg * 2;
                    float* dd = d[2 * ng + hf];
                    float o0 = silu_fast(dd[0] + rad1 * s.w512[c] + s.vbe1[c]);
                    float o1 = silu_fast(dd[1] + rad1 * s.w512[c + 1] + s.vbe1[c + 1]);
                    float o2 = silu_fast(dd[2] + rad2 * s.w512[c] + s.vbe1[c]);
                    float o3 = silu_fast(dd[3] + rad2 * s.w512[c + 1] + s.vbe1[c + 1]);
                    stpair(s.Xh, s.Xl, r1, c, o0, o1);
                    stpair(s.Xh, s.Xl, r2, c, o2, o3);
                }
            }
        }
        __syncthreads();
    }

    // ============ GEMM2 (We2) then GEMM3 (Wc1): K=256, two M-passes ==========
    const int mwid = wid & 3, nh = wid >> 2;
    for (int gm = 0; gm < 2; gm++) {
        const __half* Wh = gm ? g_Wch : g_W2h;
        const __half* Wl = gm ? g_Wcl : g_W2l;
        for (int mh = 0; mh < 2; mh++) {
#pragma unroll
            for (int i = 0; i < 16; i++)
#pragma unroll
                for (int j = 0; j < 4; j++) d[i][j] = 0.0f;

            const u32 aoff = ((u32)(mh * 64 + mwid * 16 + aRow) * 264 + aK8) * 2;
            const u32 b2h = smem_u32(BH2) + ((u32)(nh * 128 + bRow) * 40 + bK8) * 2;
            const u32 b2l = smem_u32(BL2) + ((u32)(nh * 128 + bRow) * 40 + bK8) * 2;

            uint4 pb2[8];
            auto loadG2 = [&](int kc) {
                const uint4* bh4 = (const uint4*)(Wh + (size_t)tid * 256 + kc * 32);
                const uint4* bl4 = (const uint4*)(Wl + (size_t)tid * 256 + kc * 32);
#pragma unroll
                for (int j = 0; j < 4; j++) { pb2[j] = bh4[j]; pb2[4 + j] = bl4[j]; }
            };
            auto storeG2 = [&]() {
#pragma unroll
                for (int j = 0; j < 4; j++) {
                    *(uint4*)&BH2[tid * 40 + j * 8] = pb2[j];
                    *(uint4*)&BL2[tid * 40 + j * 8] = pb2[4 + j];
                }
            };
            loadG2(0); storeG2(); __syncthreads();

            for (int kc = 0; kc < 8; kc++) {
                if (kc < 7) loadG2(kc + 1);
#pragma unroll
                for (int ks = 0; ks < 2; ks++) {
                    u32 ah[4], al[4];
                    ldsm4(ah, xh_b + aoff + (kc * 32 + ks * 16) * 2);
                    ldsm4(al, xl_b + aoff + (kc * 32 + ks * 16) * 2);
#pragma unroll
                    for (int ng = 0; ng < 8; ng++) {
                        u32 bh[4], bl[4];
                        ldsm4(bh, b2h + ng * 1280 + ks * 32);
                        ldsm4(bl, b2l + ng * 1280 + ks * 32);
                        MMA6(d[2 * ng], d[2 * ng + 1], ah, al, bh, bl);
                    }
                }
                __syncthreads();
                if (kc < 7) { storeG2(); __syncthreads(); }
            }

            int rr1 = mh * 64 + mwid * 16 + g, rr2 = rr1 + 8;
            if (gm == 0) {
                // epilogue 2: edge_feat = silu(D + be2); atomics to aggH; rewrite X
                int ri1 = s.rowI[rr1], ri2 = s.rowI[rr2];
#pragma unroll
                for (int ng = 0; ng < 8; ng++) {
#pragma unroll
                    for (int hf = 0; hf < 2; hf++) {
                        int c = nh * 128 + ng * 16 + hf * 8 + tg * 2;
                        float* dd = d[2 * ng + hf];
                        float o0 = silu_fast(dd[0] + s.vbe2[c]);
                        float o1 = silu_fast(dd[1] + s.vbe2[c + 1]);
                        float o2 = silu_fast(dd[2] + s.vbe2[c]);
                        float o3 = silu_fast(dd[3] + s.vbe2[c + 1]);
                        atomicAdd(&g_aggH[(size_t)ri1 * 256 + c], o0);
                        atomicAdd(&g_aggH[(size_t)ri1 * 256 + c + 1], o1);
                        atomicAdd(&g_aggH[(size_t)ri2 * 256 + c], o2);
                        atomicAdd(&g_aggH[(size_t)ri2 * 256 + c + 1], o3);
                        stpair(s.Xh, s.Xl, rr1, c, o0, o1);
                        stpair(s.Xh, s.Xl, rr2, c, o2, o3);
                    }
                }
            } else {
                // epilogue 3: partial dot(silu(D + bc1), wc2)
                float p1 = 0.0f, p2 = 0.0f;
#pragma unroll
                for (int ng = 0; ng < 8; ng++) {
#pragma unroll
                    for (int hf = 0; hf < 2; hf++) {
                        int c = nh * 128 + ng * 16 + hf * 8 + tg * 2;
                        float* dd = d[2 * ng + hf];
                        p1 = fmaf(silu_fast(dd[0] + s.vbc1[c]), s.vwc2[c], p1);
                        p1 = fmaf(silu_fast(dd[1] + s.vbc1[c + 1]), s.vwc2[c + 1], p1);
                        p2 = fmaf(silu_fast(dd[2] + s.vbc1[c]), s.vwc2[c], p2);
                        p2 = fmaf(silu_fast(dd[3] + s.vbc1[c + 1]), s.vwc2[c + 1], p2);
                    }
                }
                p1 += __shfl_xor_sync(0xFFFFFFFF, p1, 1);
                p1 += __shfl_xor_sync(0xFFFFFFFF, p1, 2);
                p2 += __shfl_xor_sync(0xFFFFFFFF, p2, 1);
                p2 += __shfl_xor_sync(0xFFFFFFFF, p2, 2);
                if (tg == 0) {
                    s.P[rr1 * 2 + nh] = p1;
                    s.P[rr2 * 2 + nh] = p2;
                }
            }
            __syncthreads();
        }
    }

    // coord atomics
    if (tid < 128) {
        float scal = s.P[tid * 2] + s.P[tid * 2 + 1] + __ldg(bc2);
        int ri = s.rowI[tid];
        atomicAdd(&g_aggC[ri * 3 + 0], s.cd[tid * 3 + 0] * scal);
        atomicAdd(&g_aggC[ri * 3 + 1], s.cd[tid * 3 + 1] * scal);
        atomicAdd(&g_aggC[ri * 3 + 2], s.cd[tid * 3 + 2] * scal);
        atomicAdd(&g_cnt[ri], 1.0f);
    }
}

// ---------------- node kernel (fp32 FFMA2, MUFU-free silu) ----------------
__device__ __forceinline__ ull pack_dup(float a) { ull r; asm("mov.b64 %0,{%1,%1};" : "=l"(r) : "f"(a)); return r; }
__device__ __forceinline__ float2 unpack2(ull v) { float2 r; asm("mov.b64 {%0,%1},%2;" : "=f"(r.x), "=f"(r.y) : "l"(v)); return r; }
__device__ __forceinline__ void fma2(ull& d, ull a, ull b) { asm("fma.rn.f32x2 %0,%1,%2,%0;" : "+l"(d) : "l"(a), "l"(b)); }

template <int AS>
__device__ __forceinline__ void mma_chunk(const float* __restrict__ A, const float* __restrict__ B,
                                          ull acc[4][8], int tx, int r0) {
#pragma unroll 8
    for (int k = 0; k < 32; k++) {
        ull ap[4];
#pragma unroll
        for (int r = 0; r < 4; r++) ap[r] = pack_dup(A[(r0 + r) * AS + k]);
        const float* brow = B + k * 256 + 4 * tx;
#pragma unroll
        for (int jj = 0; jj < 4; jj++) {
            ulonglong2 bv = *reinterpret_cast<const ulonglong2*>(brow + 64 * jj);
#pragma unroll
            for (int r = 0; r < 4; r++) { fma2(acc[r][2 * jj], ap[r], bv.x); fma2(acc[r][2 * jj + 1], ap[r], bv.y); }
        }
    }
}

struct __align__(16) NSm { float X[64 * 260]; float B[32 * 256]; float A[64 * 33]; };

__global__ __launch_bounds__(256, 2) void node_kernel(
    const float* __restrict__ h, const float* __restrict__ coord,
    const float* __restrict__ Wn1, const float* __restrict__ bn1,
    const float* __restrict__ Wn2, const float* __restrict__ bn2,
    float* __restrict__ out) {
    extern __shared__ char smem_raw[];
    NSm& s = *reinterpret_cast<NSm*>(smem_raw);
    const int tid = threadIdx.x, tx = tid & 15, ty = tid >> 4, r0 = ty * 4;
    const int nb = blockIdx.x * 64;
    ull acc[4][8];
#pragma unroll
    for (int r = 0; r < 4; r++)
#pragma unroll
        for (int j = 0; j < 8; j++) acc[r][j] = 0ULL;
    const int rr = tid >> 2, kk = (tid & 3) * 8;
    const int nrow = nb + rr;
    const bool vA = nrow < Nn;

    for (int kc = 0; kc < 16; kc++) {
        const int kb = kc * 32;
        float4 v0 = make_float4(0.f, 0.f, 0.f, 0.f), v1 = v0;
        if (vA) {
            const float* src = (kc < 8) ? h + (size_t)nrow * 256 + kb + kk
                                        : g_aggH + (size_t)nrow * 256 + (kb - 256) + kk;
            v0 = *reinterpret_cast<const float4*>(src);
            v1 = *reinterpret_cast<const float4*>(src + 4);
        }
        float* da = &s.A[rr * 33 + kk];
        da[0] = v0.x; da[1] = v0.y; da[2] = v0.z; da[3] = v0.w;
        da[4] = v1.x; da[5] = v1.y; da[6] = v1.z; da[7] = v1.w;
        const float4* wsrc = reinterpret_cast<const float4*>(Wn1 + (size_t)kb * 256);
        float4* wdst = reinterpret_cast<float4*>(s.B);
#pragma unroll
        for (int i = 0; i < 8; i++) wdst[tid + 256 * i] = wsrc[tid + 256 * i];
        __syncthreads();
        mma_chunk<33>(&s.A[0], s.B, acc, tx, r0);
        __syncthreads();
    }
#pragma unroll
    for (int r = 0; r < 4; r++)
#pragma unroll
        for (int jj = 0; jj < 4; jj++) {
            int c0 = 4 * tx + 64 * jj;
            float2 p0 = unpack2(acc[r][2 * jj]), p1 = unpack2(acc[r][2 * jj + 1]);
            float4 o;
            o.x = silu_fast(p0.x + __ldg(&bn1[c0 + 0]));
            o.y = silu_fast(p0.y + __ldg(&bn1[c0 + 1]));
            o.z = silu_fast(p1.x + __ldg(&bn1[c0 + 2]));
            o.w = silu_fast(p1.y + __ldg(&bn1[c0 + 3]));
            *reinterpret_cast<float4*>(&s.X[(r0 + r) * 260 + c0]) = o;
            acc[r][2 * jj] = 0ULL; acc[r][2 * jj + 1] = 0ULL;
        }
    __syncthreads();
    for (int kc = 0; kc < 8; kc++) {
        const int kb = kc * 32;
        const float4* wsrc = reinterpret_cast<const float4*>(Wn2 + (size_t)kb * 256);
        float4* wdst = reinterpret_cast<float4*>(s.B);
#pragma unroll
        for (int i = 0; i < 8; i++) wdst[tid + 256 * i] = wsrc[tid + 256 * i];
        __syncthreads();
        mma_chunk<260>(&s.X[kb], s.B, acc, tx, r0);
        __syncthreads();
    }
#pragma unroll
    for (int r = 0; r < 4; r++) {
        int n = nb + r0 + r;
        if (n < Nn) {
#pragma unroll
            for (int jj = 0; jj < 4; jj++) {
                int c0 = 4 * tx + 64 * jj;
                float2 p0 = unpack2(acc[r][2 * jj]), p1 = unpack2(acc[r][2 * jj + 1]);
                float4 o;
                o.x = p0.x + __ldg(&bn2[c0 + 0]); o.y = p0.y + __ldg(&bn2[c0 + 1]);
                o.z = p1.x + __ldg(&bn2[c0 + 2]); o.w = p1.y + __ldg(&bn2[c0 + 3]);
                *reinterpret_cast<float4*>(&out[(size_t)n * 256 + c0]) = o;
            }
        }
    }
    if (tid < 64) {
        int n = nb + tid;
        if (n < Nn) {
            float inv = 1.0f / fmaxf(g_cnt[n], 1.0f);
#pragma unroll
            for (int dd = 0; dd < 3; dd++)
                out[(size_t)Nn * 256 + n * 3 + dd] = coord[n * 3 + dd] + g_aggC[n * 3 + dd] * inv;
        }
    }
}

// ---------------------------------------------------------------------------
extern "C" void kernel_launch(void* const* d_in, const int* in_sizes, int n_in,
                              void* d_out, int out_size) {
    const float* h     = (const float*)d_in[0];
    const float* coord = (const float*)d_in[1];
    const int*   ei    = (const int*)d_in[2];
    const float* We1   = (const float*)d_in[3];
    const float* be1   = (const float*)d_in[4];
    const float* We2   = (const float*)d_in[5];
    const float* be2   = (const float*)d_in[6];
    const float* Wn1   = (const float*)d_in[7];
    const float* bn1   = (const float*)d_in[8];
    const float* Wn2   = (const float*)d_in[9];
    const float* bn2   = (const float*)d_in[10];
    const float* Wc1   = (const float*)d_in[11];
    const float* bc1   = (const float*)d_in[12];
    const float* Wc2   = (const float*)d_in[13];
    const float* bc2   = (const float*)d_in[14];
    float* out = (float*)d_out;

    cudaFuncSetAttribute(edge_kernel, cudaFuncAttributeMaxDynamicSharedMemorySize, (int)sizeof(ESm));
    cudaFuncSetAttribute(node_kernel, cudaFuncAttributeMaxDynamicSharedMemorySize, (int)sizeof(NSm));

    zero_kernel<<<1280, 256>>>();
    prep_h<<<(Nn * 256 + 255) / 256, 256>>>(h);
    prep_w<<<(512 * 256 + 255) / 256, 256>>>(We1, 512, 0);
    prep_w<<<(256 * 256 + 255) / 256, 256>>>(We2, 256, 1);
    prep_w<<<(256 * 256 + 255) / 256, 256>>>(Wc1, 256, 2);
    edge_kernel<<<Ee / 128, 256, sizeof(ESm)>>>(coord, ei, We1, be1, be2, bc1, Wc2, bc2);
    node_kernel<<<(Nn + 63) / 64, 256, sizeof(NSm)>>>(h, coord, Wn1, bn1, Wn2, bn2, out);
}

// round 9
// speedup vs baseline: 2.6264x; 1.9366x over previous
#include <cuda_runtime.h>
#include <cuda_fp16.h>
#include <cstdint>

#define Nn 10000
#define Ee 320000

typedef unsigned long long ull;
typedef unsigned int u32;

// ---------------- device scratch ----------------
__device__ float g_aggH[Nn * 256];
__device__ float g_aggC[Nn * 3];
__device__ float g_cnt[Nn];
__device__ __align__(16) float g_P[(size_t)Nn * 512];
__device__ __align__(16) __half g_W2h[256 * 256];
__device__ __align__(16) __half g_W2l[256 * 256];
__device__ __align__(16) __half g_Wch[256 * 256];
__device__ __align__(16) __half g_Wcl[256 * 256];

// ---------------- helpers ----------------
__device__ __forceinline__ u32 smem_u32(const void* p) {
    u32 a;
    asm("{ .reg .u64 t; cvta.to.shared.u64 t, %1; cvt.u32.u64 %0, t; }" : "=r"(a) : "l"(p));
    return a;
}
__device__ __forceinline__ void ldsm4(u32* r, u32 addr) {
    asm volatile("ldmatrix.sync.aligned.m8n8.x4.shared.b16 {%0,%1,%2,%3},[%4];"
                 : "=r"(r[0]), "=r"(r[1]), "=r"(r[2]), "=r"(r[3]) : "r"(addr));
}
__device__ __forceinline__ void mma16816(float* d, const u32* a, const u32* b) {
    asm volatile(
        "mma.sync.aligned.m16n8k16.row.col.f32.f16.f16.f32 "
        "{%0,%1,%2,%3},{%4,%5,%6,%7},{%8,%9},{%0,%1,%2,%3};"
        : "+f"(d[0]), "+f"(d[1]), "+f"(d[2]), "+f"(d[3])
        : "r"(a[0]), "r"(a[1]), "r"(a[2]), "r"(a[3]), "r"(b[0]), "r"(b[1]));
}
#define MMA6(d0p, d1p, ah, al, bh, bl)   \
    mma16816(d0p, ah, bh);               \
    mma16816(d0p, ah, bl);               \
    mma16816(d0p, al, bh);               \
    mma16816(d1p, ah, (bh) + 2);         \
    mma16816(d1p, ah, (bl) + 2);         \
    mma16816(d1p, al, (bh) + 2);

// MUFU-free silu
__device__ __forceinline__ float silu_fast(float x) {
    float v = fmaxf(-fabsf(x) * 1.4426950408889634f, -30.0f);
    float r = v + 12582912.0f;
    int ni = __float_as_int(r) - 0x4B400000;
    float f = v - (r - 12582912.0f);
    float p = 1.3333558146e-3f;
    p = fmaf(p, f, 9.6181291076e-3f);
    p = fmaf(p, f, 5.5504108664e-2f);
    p = fmaf(p, f, 2.4015967802e-1f);
    p = fmaf(p, f, 6.9314718056e-1f);
    p = fmaf(p, f, 1.0f);
    float z = __int_as_float(__float_as_int(p) + (ni << 23));
    float d = 1.0f + z;
    float y = __int_as_float(0x7EF311C3 - __float_as_int(d));
    y = y * fmaf(-d, y, 2.0f);
    y = y * fmaf(-d, y, 2.0f);
    y = y * fmaf(-d, y, 2.0f);
    float sig = (x >= 0.0f) ? y : (1.0f - y);
    return x * sig;
}

// ---------------- fp32 FFMA2 GEMM pieces ----------------
__device__ __forceinline__ ull pack_dup(float a) { ull r; asm("mov.b64 %0,{%1,%1};" : "=l"(r) : "f"(a)); return r; }
__device__ __forceinline__ float2 unpack2(ull v) { float2 r; asm("mov.b64 {%0,%1},%2;" : "=f"(r.x), "=f"(r.y) : "l"(v)); return r; }
__device__ __forceinline__ void fma2(ull& d, ull a, ull b) { asm("fma.rn.f32x2 %0,%1,%2,%0;" : "+l"(d) : "l"(a), "l"(b)); }

template <int AS>
__device__ __forceinline__ void mma_chunk(const float* __restrict__ A, const float* __restrict__ B,
                                          ull acc[4][8], int tx, int r0) {
#pragma unroll 8
    for (int k = 0; k < 32; k++) {
        ull ap[4];
#pragma unroll
        for (int r = 0; r < 4; r++) ap[r] = pack_dup(A[(r0 + r) * AS + k]);
        const float* brow = B + k * 256 + 4 * tx;
#pragma unroll
        for (int jj = 0; jj < 4; jj++) {
            ulonglong2 bv = *reinterpret_cast<const ulonglong2*>(brow + 64 * jj);
#pragma unroll
            for (int r = 0; r < 4; r++) { fma2(acc[r][2 * jj], ap[r], bv.x); fma2(acc[r][2 * jj + 1], ap[r], bv.y); }
        }
    }
}

// ---------------- prep kernels ----------------
__global__ void zero_kernel() {
    int idx = blockIdx.x * 256 + threadIdx.x, stride = gridDim.x * 256;
    for (int i = idx; i < Nn * 256; i += stride) g_aggH[i] = 0.0f;
    for (int i = idx; i < Nn * 3; i += stride) g_aggC[i] = 0.0f;
    for (int i = idx; i < Nn; i += stride) g_cnt[i] = 0.0f;
}
__global__ void prep_w(const float* __restrict__ W, int which) {
    __half *oh, *ol;
    if (which == 1) { oh = g_W2h; ol = g_W2l; }
    else            { oh = g_Wch; ol = g_Wcl; }
    int i = blockIdx.x * 256 + threadIdx.x;
    if (i >= 256 * 256) return;
    int k = i >> 8, n = i & 255;
    float v = W[i];
    __half hb = __float2half_rn(v);
    oh[(size_t)n * 256 + k] = hb;
    ol[(size_t)n * 256 + k] = __float2half_rn(v - __half2float(hb));
}

// ---------------- P = h @ [We1_top | We1_bot]  (fp32 exact) ----------------
struct __align__(16) PSm { float B[32 * 256]; float A[64 * 33]; };
__global__ __launch_bounds__(256, 2) void pcomp_kernel(const float* __restrict__ h,
                                                       const float* __restrict__ We1) {
    extern __shared__ char smr[];
    PSm& s = *reinterpret_cast<PSm*>(smr);
    const int tid = threadIdx.x, tx = tid & 15, ty = tid >> 4, r0 = ty * 4;
    const int nb = blockIdx.x * 64, hy = blockIdx.y;
    ull acc[4][8];
#pragma unroll
    for (int r = 0; r < 4; r++)
#pragma unroll
        for (int j = 0; j < 8; j++) acc[r][j] = 0ULL;
    const int rr = tid >> 2, kk = (tid & 3) * 8;
    const int nrow = nb + rr;
    const bool vA = nrow < Nn;

    for (int kc = 0; kc < 8; kc++) {
        const int kb = kc * 32;
        float4 v0 = make_float4(0.f, 0.f, 0.f, 0.f), v1 = v0;
        if (vA) {
            const float* src = h + (size_t)nrow * 256 + kb + kk;
            v0 = *reinterpret_cast<const float4*>(src);
            v1 = *reinterpret_cast<const float4*>(src + 4);
        }
        float* da = &s.A[rr * 33 + kk];
        da[0] = v0.x; da[1] = v0.y; da[2] = v0.z; da[3] = v0.w;
        da[4] = v1.x; da[5] = v1.y; da[6] = v1.z; da[7] = v1.w;
        const float4* wsrc = reinterpret_cast<const float4*>(We1 + (size_t)(hy * 256 + kb) * 256);
        float4* wdst = reinterpret_cast<float4*>(s.B);
#pragma unroll
        for (int i = 0; i < 8; i++) wdst[tid + 256 * i] = wsrc[tid + 256 * i];
        __syncthreads();
        mma_chunk<33>(&s.A[0], s.B, acc, tx, r0);
        __syncthreads();
    }
#pragma unroll
    for (int r = 0; r < 4; r++) {
        int n = nb + r0 + r;
        if (n < Nn) {
#pragma unroll
            for (int jj = 0; jj < 4; jj++) {
                int c0 = 4 * tx + 64 * jj;
                float2 p0 = unpack2(acc[r][2 * jj]), p1 = unpack2(acc[r][2 * jj + 1]);
                *reinterpret_cast<float4*>(&g_P[(size_t)n * 512 + hy * 256 + c0]) =
                    make_float4(p0.x, p0.y, p1.x, p1.y);
            }
        }
    }
}

// ---------------- fused edge kernel (512 threads) ----------------
struct __align__(128) ESm {
    __half Xh[128 * 264];
    __half Xl[128 * 264];
    __half BH2[256 * 40];
    __half BL2[256 * 40];
    float w512[256], vbe1[256], vbe2[256], vbc1[256], vwc2[256];
    float rad[128], cd[384], P[256];
    int rowI[128], colI[128];
};

__device__ __forceinline__ void stpair(__half* X_h, __half* X_l, int r, int c, float o0, float o1) {
    __half h0 = __float2half_rn(o0), h1 = __float2half_rn(o1);
    __half l0 = __float2half_rn(o0 - __half2float(h0));
    __half l1 = __float2half_rn(o1 - __half2float(h1));
    *reinterpret_cast<__half2*>(&X_h[r * 264 + c]) = __halves2half2(h0, h1);
    *reinterpret_cast<__half2*>(&X_l[r * 264 + c]) = __halves2half2(l0, l1);
}

__global__ __launch_bounds__(512, 1) void edge_kernel(
    const float* __restrict__ coord, const int* __restrict__ ei,
    const float* __restrict__ We1, const float* __restrict__ be1,
    const float* __restrict__ be2, const float* __restrict__ bc1,
    const float* __restrict__ Wc2, const float* __restrict__ bc2) {
    extern __shared__ char smr[];
    ESm& s = *reinterpret_cast<ESm*>(smr);
    const int tid = threadIdx.x, wid = tid >> 5, lane = tid & 31;
    const int g = lane >> 2, tg = lane & 3;
    const int eb = blockIdx.x * 128;

    if (tid < 128) {
        int e = eb + tid;
        int ri = ei[e], ci = ei[Ee + e];
        s.rowI[tid] = ri; s.colI[tid] = ci;
        float dx = coord[ri * 3 + 0] - coord[ci * 3 + 0];
        float dy = coord[ri * 3 + 1] - coord[ci * 3 + 1];
        float dz = coord[ri * 3 + 2] - coord[ci * 3 + 2];
        s.cd[tid * 3 + 0] = dx; s.cd[tid * 3 + 1] = dy; s.cd[tid * 3 + 2] = dz;
        s.rad[tid] = dx * dx + dy * dy + dz * dz;
    }
    if (tid < 256) {
        s.w512[tid] = We1[512 * 256 + tid];
        s.vbe1[tid] = be1[tid];
        s.vbe2[tid] = be2[tid];
        s.vbc1[tid] = bc1[tid];
        s.vwc2[tid] = Wc2[tid];
    }
    __syncthreads();

    // ---- phase 1: X = silu(P[row] + P[col|off256] + rad*w512 + be1) ----
    {
        int e = tid >> 2, q = (tid & 3) * 64;
        const float4* pr = (const float4*)(g_P + (size_t)s.rowI[e] * 512 + q);
        const float4* pc = (const float4*)(g_P + (size_t)s.colI[e] * 512 + 256 + q);
        float radr = s.rad[e];
#pragma unroll
        for (int jj = 0; jj < 16; jj++) {
            float4 a = pr[jj], b = pc[jj];
            int c = q + jj * 4;
            float o0 = silu_fast(a.x + b.x + radr * s.w512[c + 0] + s.vbe1[c + 0]);
            float o1 = silu_fast(a.y + b.y + radr * s.w512[c + 1] + s.vbe1[c + 1]);
            float o2 = silu_fast(a.z + b.z + radr * s.w512[c + 2] + s.vbe1[c + 2]);
            float o3 = silu_fast(a.w + b.w + radr * s.w512[c + 3] + s.vbe1[c + 3]);
            stpair(s.Xh, s.Xl, e, c, o0, o1);
            stpair(s.Xh, s.Xl, e, c + 2, o2, o3);
        }
    }
    __syncthreads();

    // ---- GEMM2 (We2) then GEMM3 (Wc1): 16 warps = 8 M-groups x 2 N-halves ----
    const int mwid = wid & 7, nh = wid >> 3;
    const int aRow = (lane & 7) + (lane & 8);
    const int aK8 = (lane & 16) ? 8 : 0;
    const int bRow = (lane & 7) + ((lane & 16) ? 8 : 0);
    const int bK8 = (lane & 8) ? 8 : 0;
    const u32 xh_b = smem_u32(s.Xh), xl_b = smem_u32(s.Xl);
    const u32 aoff = ((u32)(mwid * 16 + aRow) * 264 + aK8) * 2;
    const u32 b2h = smem_u32(s.BH2) + ((u32)(nh * 128 + bRow) * 40 + bK8) * 2;
    const u32 b2l = smem_u32(s.BL2) + ((u32)(nh * 128 + bRow) * 40 + bK8) * 2;
    const int sn = tid >> 1, sh = tid & 1;

    float d[16][4];

    for (int gm = 0; gm < 2; gm++) {
        const __half* Wh = gm ? g_Wch : g_W2h;
        const __half* Wl = gm ? g_Wcl : g_W2l;
#pragma unroll
        for (int i = 0; i < 16; i++)
#pragma unroll
            for (int j = 0; j < 4; j++) d[i][j] = 0.0f;

        uint4 pb2[4];
        auto loadB = [&](int kc) {
            const uint4* bh4 = (const uint4*)(Wh + (size_t)sn * 256 + kc * 32 + sh * 16);
            const uint4* bl4 = (const uint4*)(Wl + (size_t)sn * 256 + kc * 32 + sh * 16);
            pb2[0] = bh4[0]; pb2[1] = bh4[1]; pb2[2] = bl4[0]; pb2[3] = bl4[1];
        };
        auto storeB = [&]() {
            *(uint4*)&s.BH2[sn * 40 + sh * 16] = pb2[0];
            *(uint4*)&s.BH2[sn * 40 + sh * 16 + 8] = pb2[1];
            *(uint4*)&s.BL2[sn * 40 + sh * 16] = pb2[2];
            *(uint4*)&s.BL2[sn * 40 + sh * 16 + 8] = pb2[3];
        };
        loadB(0); storeB(); __syncthreads();

        for (int kc = 0; kc < 8; kc++) {
            if (kc < 7) loadB(kc + 1);
#pragma unroll
            for (int ks = 0; ks < 2; ks++) {
                u32 ah[4], al[4];
                ldsm4(ah, xh_b + aoff + (kc * 32 + ks * 16) * 2);
                ldsm4(al, xl_b + aoff + (kc * 32 + ks * 16) * 2);
#pragma unroll
                for (int ng = 0; ng < 8; ng++) {
                    u32 bh[4], bl[4];
                    ldsm4(bh, b2h + ng * 1280 + ks * 32);
                    ldsm4(bl, b2l + ng * 1280 + ks * 32);
                    MMA6(d[2 * ng], d[2 * ng + 1], ah, al, bh, bl);
                }
            }
            __syncthreads();
            if (kc < 7) { storeB(); __syncthreads(); }
        }

        int rr1 = mwid * 16 + g, rr2 = rr1 + 8;
        if (gm == 0) {
            // epilogue 2: edge_feat = silu(D+be2); atomics to aggH; rewrite X
            int ri1 = s.rowI[rr1], ri2 = s.rowI[rr2];
#pragma unroll
            for (int ng = 0; ng < 8; ng++) {
#pragma unroll
                for (int hf = 0; hf < 2; hf++) {
                    int c = nh * 128 + ng * 16 + hf * 8 + tg * 2;
                    float* dd = d[2 * ng + hf];
                    float o0 = silu_fast(dd[0] + s.vbe2[c]);
                    float o1 = silu_fast(dd[1] + s.vbe2[c + 1]);
                    float o2 = silu_fast(dd[2] + s.vbe2[c]);
                    float o3 = silu_fast(dd[3] + s.vbe2[c + 1]);
                    atomicAdd(&g_aggH[(size_t)ri1 * 256 + c], o0);
                    atomicAdd(&g_aggH[(size_t)ri1 * 256 + c + 1], o1);
                    atomicAdd(&g_aggH[(size_t)ri2 * 256 + c], o2);
                    atomicAdd(&g_aggH[(size_t)ri2 * 256 + c + 1], o3);
                    stpair(s.Xh, s.Xl, rr1, c, o0, o1);
                    stpair(s.Xh, s.Xl, rr2, c, o2, o3);
                }
            }
        } else {
            // epilogue 3: partial dot(silu(D+bc1), wc2)
            float p1 = 0.0f, p2 = 0.0f;
#pragma unroll
            for (int ng = 0; ng < 8; ng++) {
#pragma unroll
                for (int hf = 0; hf < 2; hf++) {
                    int c = nh * 128 + ng * 16 + hf * 8 + tg * 2;
                    float* dd = d[2 * ng + hf];
                    p1 = fmaf(silu_fast(dd[0] + s.vbc1[c]), s.vwc2[c], p1);
                    p1 = fmaf(silu_fast(dd[1] + s.vbc1[c + 1]), s.vwc2[c + 1], p1);
                    p2 = fmaf(silu_fast(dd[2] + s.vbc1[c]), s.vwc2[c], p2);
                    p2 = fmaf(silu_fast(dd[3] + s.vbc1[c + 1]), s.vwc2[c + 1], p2);
                }
            }
            p1 += __shfl_xor_sync(0xFFFFFFFF, p1, 1);
            p1 += __shfl_xor_sync(0xFFFFFFFF, p1, 2);
            p2 += __shfl_xor_sync(0xFFFFFFFF, p2, 1);
            p2 += __shfl_xor_sync(0xFFFFFFFF, p2, 2);
            if (tg == 0) {
                s.P[rr1 * 2 + nh] = p1;
                s.P[rr2 * 2 + nh] = p2;
            }
        }
        __syncthreads();
    }

    // coord atomics
    if (tid < 128) {
        float scal = s.P[tid * 2] + s.P[tid * 2 + 1] + __ldg(bc2);
        int ri = s.rowI[tid];
        atomicAdd(&g_aggC[ri * 3 + 0], s.cd[tid * 3 + 0] * scal);
        atomicAdd(&g_aggC[ri * 3 + 1], s.cd[tid * 3 + 1] * scal);
        atomicAdd(&g_aggC[ri * 3 + 2], s.cd[tid * 3 + 2] * scal);
        atomicAdd(&g_cnt[ri], 1.0f);
    }
}

// ---------------- node kernel (unchanged from R6) ----------------
struct __align__(16) NSm { float X[64 * 260]; float B[32 * 256]; float A[64 * 33]; };

__global__ __launch_bounds__(256, 2) void node_kernel(
    const float* __restrict__ h, const float* __restrict__ coord,
    const float* __restrict__ Wn1, const float* __restrict__ bn1,
    const float* __restrict__ Wn2, const float* __restrict__ bn2,
    float* __restrict__ out) {
    extern __shared__ char smem_raw[];
    NSm& s = *reinterpret_cast<NSm*>(smem_raw);
    const int tid = threadIdx.x, tx = tid & 15, ty = tid >> 4, r0 = ty * 4;
    const int nb = blockIdx.x * 64;
    ull acc[4][8];
#pragma unroll
    for (int r = 0; r < 4; r++)
#pragma unroll
        for (int j = 0; j < 8; j++) acc[r][j] = 0ULL;
    const int rr = tid >> 2, kk = (tid & 3) * 8;
    const int nrow = nb + rr;
    const bool vA = nrow < Nn;

    for (int kc = 0; kc < 16; kc++) {
        const int kb = kc * 32;
        float4 v0 = make_float4(0.f, 0.f, 0.f, 0.f), v1 = v0;
        if (vA) {
            const float* src = (kc < 8) ? h + (size_t)nrow * 256 + kb + kk
                                        : g_aggH + (size_t)nrow * 256 + (kb - 256) + kk;
            v0 = *reinterpret_cast<const float4*>(src);
            v1 = *reinterpret_cast<const float4*>(src + 4);
        }
        float* da = &s.A[rr * 33 + kk];
        da[0] = v0.x; da[1] = v0.y; da[2] = v0.z; da[3] = v0.w;
        da[4] = v1.x; da[5] = v1.y; da[6] = v1.z; da[7] = v1.w;
        const float4* wsrc = reinterpret_cast<const float4*>(Wn1 + (size_t)kb * 256);
        float4* wdst = reinterpret_cast<float4*>(s.B);
#pragma unroll
        for (int i = 0; i < 8; i++) wdst[tid + 256 * i] = wsrc[tid + 256 * i];
        __syncthreads();
        mma_chunk<33>(&s.A[0], s.B, acc, tx, r0);
        __syncthreads();
    }
#pragma unroll
    for (int r = 0; r < 4; r++)
#pragma unroll
        for (int jj = 0; jj < 4; jj++) {
            int c0 = 4 * tx + 64 * jj;
            float2 p0 = unpack2(acc[r][2 * jj]), p1 = unpack2(acc[r][2 * jj + 1]);
            float4 o;
            o.x = silu_fast(p0.x + __ldg(&bn1[c0 + 0]));
            o.y = silu_fast(p0.y + __ldg(&bn1[c0 + 1]));
            o.z = silu_fast(p1.x + __ldg(&bn1[c0 + 2]));
            o.w = silu_fast(p1.y + __ldg(&bn1[c0 + 3]));
            *reinterpret_cast<float4*>(&s.X[(r0 + r) * 260 + c0]) = o;
            acc[r][2 * jj] = 0ULL; acc[r][2 * jj + 1] = 0ULL;
        }
    __syncthreads();
    for (int kc = 0; kc < 8; kc++) {
        const int kb = kc * 32;
        const float4* wsrc = reinterpret_cast<const float4*>(Wn2 + (size_t)kb * 256);
        float4* wdst = reinterpret_cast<float4*>(s.B);
#pragma unroll
        for (int i = 0; i < 8; i++) wdst[tid + 256 * i] = wsrc[tid + 256 * i];
        __syncthreads();
        mma_chunk<260>(&s.X[kb], s.B, acc, tx, r0);
        __syncthreads();
    }
#pragma unroll
    for (int r = 0; r < 4; r++) {
        int n = nb + r0 + r;
        if (n < Nn) {
#pragma unroll
            for (int jj = 0; jj < 4; jj++) {
                int c0 = 4 * tx + 64 * jj;
                float2 p0 = unpack2(acc[r][2 * jj]), p1 = unpack2(acc[r][2 * jj + 1]);
                float4 o;
                o.x = p0.x + __ldg(&bn2[c0 + 0]); o.y = p0.y + __ldg(&bn2[c0 + 1]);
                o.z = p1.x + __ldg(&bn2[c0 + 2]); o.w = p1.y + __ldg(&bn2[c0 + 3]);
                *reinterpret_cast<float4*>(&out[(size_t)n * 256 + c0]) = o;
            }
        }
    }
    if (tid < 64) {
        int n = nb + tid;
        if (n < Nn) {
            float inv = 1.0f / fmaxf(g_cnt[n], 1.0f);
#pragma unroll
            for (int dd = 0; dd < 3; dd++)
                out[(size_t)Nn * 256 + n * 3 + dd] = coord[n * 3 + dd] + g_aggC[n * 3 + dd] * inv;
        }
    }
}

// ---------------------------------------------------------------------------
extern "C" void kernel_launch(void* const* d_in, const int* in_sizes, int n_in,
                              void* d_out, int out_size) {
    const float* h     = (const float*)d_in[0];
    const float* coord = (const float*)d_in[1];
    const int*   ei    = (const int*)d_in[2];
    const float* We1   = (const float*)d_in[3];
    const float* be1   = (const float*)d_in[4];
    const float* We2   = (const float*)d_in[5];
    const float* be2   = (const float*)d_in[6];
    const float* Wn1   = (const float*)d_in[7];
    const float* bn1   = (const float*)d_in[8];
    const float* Wn2   = (const float*)d_in[9];
    const float* bn2   = (const float*)d_in[10];
    const float* Wc1   = (const float*)d_in[11];
    const float* bc1   = (const float*)d_in[12];
    const float* Wc2   = (const float*)d_in[13];
    const float* bc2   = (const float*)d_in[14];
    float* out = (float*)d_out;

    cudaFuncSetAttribute(edge_kernel, cudaFuncAttributeMaxDynamicSharedMemorySize, (int)sizeof(ESm));
    cudaFuncSetAttribute(node_kernel, cudaFuncAttributeMaxDynamicSharedMemorySize, (int)sizeof(NSm));
    cudaFuncSetAttribute(pcomp_kernel, cudaFuncAttributeMaxDynamicSharedMemorySize, (int)sizeof(PSm));

    zero_kernel<<<1280, 256>>>();
    prep_w<<<256, 256>>>(We2, 1);
    prep_w<<<256, 256>>>(Wc1, 2);
    pcomp_kernel<<<dim3((Nn + 63) / 64, 2), 256, sizeof(PSm)>>>(h, We1);
    edge_kernel<<<Ee / 128, 512, sizeof(ESm)>>>(coord, ei, We1, be1, be2, bc1, Wc2, bc2);
    node_kernel<<<(Nn + 63) / 64, 256, sizeof(NSm)>>>(h, coord, Wn1, bn1, Wn2, bn2, out);
}

// round 10
// speedup vs baseline: 3.2134x; 1.2235x over previous
#include <cuda_runtime.h>
#include <cuda_fp16.h>
#include <cstdint>

#define Nn 10000
#define Ee 320000

typedef unsigned long long ull;
typedef unsigned int u32;

// ---------------- device scratch ----------------
__device__ float g_aggH[Nn * 256];
__device__ float g_aggC[Nn * 3];
__device__ float g_cnt[Nn];
__device__ __align__(16) float g_P[(size_t)Nn * 512];
__device__ __align__(16) __half g_W2h[256 * 256];
__device__ __align__(16) __half g_W2l[256 * 256];
__device__ __align__(16) __half g_Wch[256 * 256];

// ---------------- helpers ----------------
__device__ __forceinline__ u32 smem_u32(const void* p) {
    u32 a;
    asm("{ .reg .u64 t; cvta.to.shared.u64 t, %1; cvt.u32.u64 %0, t; }" : "=r"(a) : "l"(p));
    return a;
}
__device__ __forceinline__ void ldsm4(u32* r, u32 addr) {
    asm volatile("ldmatrix.sync.aligned.m8n8.x4.shared.b16 {%0,%1,%2,%3},[%4];"
                 : "=r"(r[0]), "=r"(r[1]), "=r"(r[2]), "=r"(r[3]) : "r"(addr));
}
__device__ __forceinline__ void mma16816(float* d, const u32* a, const u32* b) {
    asm volatile(
        "mma.sync.aligned.m16n8k16.row.col.f32.f16.f16.f32 "
        "{%0,%1,%2,%3},{%4,%5,%6,%7},{%8,%9},{%0,%1,%2,%3};"
        : "+f"(d[0]), "+f"(d[1]), "+f"(d[2]), "+f"(d[3])
        : "r"(a[0]), "r"(a[1]), "r"(a[2]), "r"(a[3]), "r"(b[0]), "r"(b[1]));
}

// MUFU-free silu
__device__ __forceinline__ float silu_fast(float x) {
    float v = fmaxf(-fabsf(x) * 1.4426950408889634f, -30.0f);
    float r = v + 12582912.0f;
    int ni = __float_as_int(r) - 0x4B400000;
    float f = v - (r - 12582912.0f);
    float p = 1.3333558146e-3f;
    p = fmaf(p, f, 9.6181291076e-3f);
    p = fmaf(p, f, 5.5504108664e-2f);
    p = fmaf(p, f, 2.4015967802e-1f);
    p = fmaf(p, f, 6.9314718056e-1f);
    p = fmaf(p, f, 1.0f);
    float z = __int_as_float(__float_as_int(p) + (ni << 23));
    float d = 1.0f + z;
    float y = __int_as_float(0x7EF311C3 - __float_as_int(d));
    y = y * fmaf(-d, y, 2.0f);
    y = y * fmaf(-d, y, 2.0f);
    y = y * fmaf(-d, y, 2.0f);
    float sig = (x >= 0.0f) ? y : (1.0f - y);
    return x * sig;
}

// ---------------- fp32 FFMA2 GEMM pieces ----------------
__device__ __forceinline__ ull pack_dup(float a) { ull r; asm("mov.b64 %0,{%1,%1};" : "=l"(r) : "f"(a)); return r; }
__device__ __forceinline__ float2 unpack2(ull v) { float2 r; asm("mov.b64 {%0,%1},%2;" : "=f"(r.x), "=f"(r.y) : "l"(v)); return r; }
__device__ __forceinline__ void fma2(ull& d, ull a, ull b) { asm("fma.rn.f32x2 %0,%1,%2,%0;" : "+l"(d) : "l"(a), "l"(b)); }

template <int AS>
__device__ __forceinline__ void mma_chunk(const float* __restrict__ A, const float* __restrict__ B,
                                          ull acc[4][8], int tx, int r0) {
#pragma unroll 8
    for (int k = 0; k < 32; k++) {
        ull ap[4];
#pragma unroll
        for (int r = 0; r < 4; r++) ap[r] = pack_dup(A[(r0 + r) * AS + k]);
        const float* brow = B + k * 256 + 4 * tx;
#pragma unroll
        for (int jj = 0; jj < 4; jj++) {
            ulonglong2 bv = *reinterpret_cast<const ulonglong2*>(brow + 64 * jj);
#pragma unroll
            for (int r = 0; r < 4; r++) { fma2(acc[r][2 * jj], ap[r], bv.x); fma2(acc[r][2 * jj + 1], ap[r], bv.y); }
        }
    }
}

// ---------------- prep kernels ----------------
__global__ void zero_kernel() {
    int idx = blockIdx.x * 256 + threadIdx.x, stride = gridDim.x * 256;
    for (int i = idx; i < Nn * 256; i += stride) g_aggH[i] = 0.0f;
    for (int i = idx; i < Nn * 3; i += stride) g_aggC[i] = 0.0f;
    for (int i = idx; i < Nn; i += stride) g_cnt[i] = 0.0f;
}
__global__ void prep_w(const float* __restrict__ W, int which) {
    int i = blockIdx.x * 256 + threadIdx.x;
    if (i >= 256 * 256) return;
    int k = i >> 8, n = i & 255;
    float v = W[i];
    __half hb = __float2half_rn(v);
    if (which == 1) {
        g_W2h[(size_t)n * 256 + k] = hb;
        g_W2l[(size_t)n * 256 + k] = __float2half_rn(v - __half2float(hb));
    } else {
        g_Wch[(size_t)n * 256 + k] = hb;
    }
}

// ---------------- P = h @ [We1_top | We1_bot]  (fp32 exact) ----------------
struct __align__(16) PSm { float B[32 * 256]; float A[64 * 33]; };
__global__ __launch_bounds__(256, 2) void pcomp_kernel(const float* __restrict__ h,
                                                       const float* __restrict__ We1) {
    extern __shared__ char smr[];
    PSm& s = *reinterpret_cast<PSm*>(smr);
    const int tid = threadIdx.x, tx = tid & 15, ty = tid >> 4, r0 = ty * 4;
    const int nb = blockIdx.x * 64, hy = blockIdx.y;
    ull acc[4][8];
#pragma unroll
    for (int r = 0; r < 4; r++)
#pragma unroll
        for (int j = 0; j < 8; j++) acc[r][j] = 0ULL;
    const int rr = tid >> 2, kk = (tid & 3) * 8;
    const int nrow = nb + rr;
    const bool vA = nrow < Nn;

    for (int kc = 0; kc < 8; kc++) {
        const int kb = kc * 32;
        float4 v0 = make_float4(0.f, 0.f, 0.f, 0.f), v1 = v0;
        if (vA) {
            const float* src = h + (size_t)nrow * 256 + kb + kk;
            v0 = *reinterpret_cast<const float4*>(src);
            v1 = *reinterpret_cast<const float4*>(src + 4);
        }
        float* da = &s.A[rr * 33 + kk];
        da[0] = v0.x; da[1] = v0.y; da[2] = v0.z; da[3] = v0.w;
        da[4] = v1.x; da[5] = v1.y; da[6] = v1.z; da[7] = v1.w;
        const float4* wsrc = reinterpret_cast<const float4*>(We1 + (size_t)(hy * 256 + kb) * 256);
        float4* wdst = reinterpret_cast<float4*>(s.B);
#pragma unroll
        for (int i = 0; i < 8; i++) wdst[tid + 256 * i] = wsrc[tid + 256 * i];
        __syncthreads();
        mma_chunk<33>(&s.A[0], s.B, acc, tx, r0);
        __syncthreads();
    }
#pragma unroll
    for (int r = 0; r < 4; r++) {
        int n = nb + r0 + r;
        if (n < Nn) {
#pragma unroll
            for (int jj = 0; jj < 4; jj++) {
                int c0 = 4 * tx + 64 * jj;
                float2 p0 = unpack2(acc[r][2 * jj]), p1 = unpack2(acc[r][2 * jj + 1]);
                *reinterpret_cast<float4*>(&g_P[(size_t)n * 512 + hy * 256 + c0]) =
                    make_float4(p0.x, p0.y, p1.x, p1.y);
            }
        }
    }
}

// ---------------- fused edge kernel (512 threads) ----------------
struct __align__(128) ESm {
    __half Xh[128 * 264];       // fp16 activations (hi only)
    __half BH[2][256 * 40];     // double-buffered weight hi
    __half BL[2][256 * 40];     // double-buffered weight lo (GEMM2 only)
    float w512[256], vbe1[256], vbe2[256], vbc1[256], vwc2[256];
    float rad[128], cd[384], P[256];
    int rowI[128], colI[128];
};

__global__ __launch_bounds__(512, 1) void edge_kernel(
    const float* __restrict__ coord, const int* __restrict__ ei,
    const float* __restrict__ We1, const float* __restrict__ be1,
    const float* __restrict__ be2, const float* __restrict__ bc1,
    const float* __restrict__ Wc2, const float* __restrict__ bc2) {
    extern __shared__ char smr[];
    ESm& s = *reinterpret_cast<ESm*>(smr);
    const int tid = threadIdx.x, wid = tid >> 5, lane = tid & 31;
    const int g = lane >> 2, tg = lane & 3;
    const int eb = blockIdx.x * 128;

    if (tid < 128) {
        int e = eb + tid;
        int ri = ei[e], ci = ei[Ee + e];
        s.rowI[tid] = ri; s.colI[tid] = ci;
        float dx = coord[ri * 3 + 0] - coord[ci * 3 + 0];
        float dy = coord[ri * 3 + 1] - coord[ci * 3 + 1];
        float dz = coord[ri * 3 + 2] - coord[ci * 3 + 2];
        s.cd[tid * 3 + 0] = dx; s.cd[tid * 3 + 1] = dy; s.cd[tid * 3 + 2] = dz;
        s.rad[tid] = dx * dx + dy * dy + dz * dz;
    }
    if (tid < 256) {
        s.w512[tid] = We1[512 * 256 + tid];
        s.vbe1[tid] = be1[tid];
        s.vbe2[tid] = be2[tid];
        s.vbc1[tid] = bc1[tid];
        s.vwc2[tid] = Wc2[tid];
    }
    __syncthreads();

    // ---- phase 1: X = silu(P[row] + P[col|off256] + rad*w512 + be1) ----
    {
        int e = tid >> 2, q = (tid & 3) * 64;
        const float4* pr = (const float4*)(g_P + (size_t)s.rowI[e] * 512 + q);
        const float4* pc = (const float4*)(g_P + (size_t)s.colI[e] * 512 + 256 + q);
        float radr = s.rad[e];
#pragma unroll
        for (int jj = 0; jj < 16; jj++) {
            float4 a = pr[jj], b = pc[jj];
            int c = q + jj * 4;
            float o0 = silu_fast(a.x + b.x + radr * s.w512[c + 0] + s.vbe1[c + 0]);
            float o1 = silu_fast(a.y + b.y + radr * s.w512[c + 1] + s.vbe1[c + 1]);
            float o2 = silu_fast(a.z + b.z + radr * s.w512[c + 2] + s.vbe1[c + 2]);
            float o3 = silu_fast(a.w + b.w + radr * s.w512[c + 3] + s.vbe1[c + 3]);
            *reinterpret_cast<__half2*>(&s.Xh[e * 264 + c]) =
                __halves2half2(__float2half_rn(o0), __float2half_rn(o1));
            *reinterpret_cast<__half2*>(&s.Xh[e * 264 + c + 2]) =
                __halves2half2(__float2half_rn(o2), __float2half_rn(o3));
        }
    }
    __syncthreads();

    // ---- GEMM2 (We2, 2-term) then GEMM3 (Wc1, 1-term) ----
    const int mwid = wid & 7, nh = wid >> 3;
    const int aRow = (lane & 7) + (lane & 8);
    const int aK8 = (lane & 16) ? 8 : 0;
    const int bRow = (lane & 7) + ((lane & 16) ? 8 : 0);
    const int bK8 = (lane & 8) ? 8 : 0;
    const u32 xh_b = smem_u32(s.Xh);
    const u32 aoff = ((u32)(mwid * 16 + aRow) * 264 + aK8) * 2;
    const u32 boffL = ((u32)(nh * 128 + bRow) * 40 + bK8) * 2;
    const u32 bh_b0 = smem_u32(s.BH[0]) + boffL, bh_b1 = smem_u32(s.BH[1]) + boffL;
    const u32 bl_b0 = smem_u32(s.BL[0]) + boffL, bl_b1 = smem_u32(s.BL[1]) + boffL;
    const int sn = tid >> 1, sh = tid & 1;

    float d[16][4];

    // =========================== GEMM2 ===========================
    {
#pragma unroll
        for (int i = 0; i < 16; i++)
#pragma unroll
            for (int j = 0; j < 4; j++) d[i][j] = 0.0f;

        uint4 pbh[2], pbl[2];
        auto loadB = [&](int kc) {
            const uint4* bh4 = (const uint4*)(g_W2h + (size_t)sn * 256 + kc * 32 + sh * 16);
            const uint4* bl4 = (const uint4*)(g_W2l + (size_t)sn * 256 + kc * 32 + sh * 16);
            pbh[0] = bh4[0]; pbh[1] = bh4[1];
            pbl[0] = bl4[0]; pbl[1] = bl4[1];
        };
        auto storeB = [&](int b) {
            *(uint4*)&s.BH[b][sn * 40 + sh * 16] = pbh[0];
            *(uint4*)&s.BH[b][sn * 40 + sh * 16 + 8] = pbh[1];
            *(uint4*)&s.BL[b][sn * 40 + sh * 16] = pbl[0];
            *(uint4*)&s.BL[b][sn * 40 + sh * 16 + 8] = pbl[1];
        };
        loadB(0); storeB(0);
        __syncthreads();

        for (int kc = 0; kc < 8; kc++) {
            if (kc < 7) loadB(kc + 1);
            const u32 bhc = (kc & 1) ? bh_b1 : bh_b0;
            const u32 blc = (kc & 1) ? bl_b1 : bl_b0;
#pragma unroll
            for (int ks = 0; ks < 2; ks++) {
                u32 ah[4];
                ldsm4(ah, xh_b + aoff + (kc * 32 + ks * 16) * 2);
#pragma unroll
                for (int ng = 0; ng < 8; ng++) {
                    u32 bh[4], bl[4];
                    ldsm4(bh, bhc + ng * 1280 + ks * 32);
                    ldsm4(bl, blc + ng * 1280 + ks * 32);
                    mma16816(d[2 * ng], ah, bh);
                    mma16816(d[2 * ng], ah, bl);
                    mma16816(d[2 * ng + 1], ah, bh + 2);
                    mma16816(d[2 * ng + 1], ah, bl + 2);
                }
            }
            if (kc < 7) storeB((kc + 1) & 1);
            __syncthreads();
        }

        // epilogue 2: edge_feat = silu(D+be2); atomics; rewrite Xh
        int rr1 = mwid * 16 + g, rr2 = rr1 + 8;
        int ri1 = s.rowI[rr1], ri2 = s.rowI[rr2];
#pragma unroll
        for (int ng = 0; ng < 8; ng++) {
#pragma unroll
            for (int hf = 0; hf < 2; hf++) {
                int c = nh * 128 + ng * 16 + hf * 8 + tg * 2;
                float* dd = d[2 * ng + hf];
                float o0 = silu_fast(dd[0] + s.vbe2[c]);
                float o1 = silu_fast(dd[1] + s.vbe2[c + 1]);
                float o2 = silu_fast(dd[2] + s.vbe2[c]);
                float o3 = silu_fast(dd[3] + s.vbe2[c + 1]);
                atomicAdd(&g_aggH[(size_t)ri1 * 256 + c], o0);
                atomicAdd(&g_aggH[(size_t)ri1 * 256 + c + 1], o1);
                atomicAdd(&g_aggH[(size_t)ri2 * 256 + c], o2);
                atomicAdd(&g_aggH[(size_t)ri2 * 256 + c + 1], o3);
                *reinterpret_cast<__half2*>(&s.Xh[rr1 * 264 + c]) =
                    __halves2half2(__float2half_rn(o0), __float2half_rn(o1));
                *reinterpret_cast<__half2*>(&s.Xh[rr2 * 264 + c]) =
                    __halves2half2(__float2half_rn(o2), __float2half_rn(o3));
            }
        }
    }
    __syncthreads();

    // =========================== GEMM3 (hi only) ===========================
    {
#pragma unroll
        for (int i = 0; i < 16; i++)
#pragma unroll
            for (int j = 0; j < 4; j++) d[i][j] = 0.0f;

        uint4 pbh[2];
        auto loadB = [&](int kc) {
            const uint4* bh4 = (const uint4*)(g_Wch + (size_t)sn * 256 + kc * 32 + sh * 16);
            pbh[0] = bh4[0]; pbh[1] = bh4[1];
        };
        auto storeB = [&](int b) {
            *(uint4*)&s.BH[b][sn * 40 + sh * 16] = pbh[0];
            *(uint4*)&s.BH[b][sn * 40 + sh * 16 + 8] = pbh[1];
        };
        loadB(0); storeB(0);
        __syncthreads();

        for (int kc = 0; kc < 8; kc++) {
            if (kc < 7) loadB(kc + 1);
            const u32 bhc = (kc & 1) ? bh_b1 : bh_b0;
#pragma unroll
            for (int ks = 0; ks < 2; ks++) {
                u32 ah[4];
                ldsm4(ah, xh_b + aoff + (kc * 32 + ks * 16) * 2);
#pragma unroll
                for (int ng = 0; ng < 8; ng++) {
                    u32 bh[4];
                    ldsm4(bh, bhc + ng * 1280 + ks * 32);
                    mma16816(d[2 * ng], ah, bh);
                    mma16816(d[2 * ng + 1], ah, bh + 2);
                }
            }
            if (kc < 7) storeB((kc + 1) & 1);
            __syncthreads();
        }

        // epilogue 3: partial dot(silu(D+bc1), wc2)
        int rr1 = mwid * 16 + g, rr2 = rr1 + 8;
        float p1 = 0.0f, p2 = 0.0f;
#pragma unroll
        for (int ng = 0; ng < 8; ng++) {
#pragma unroll
            for (int hf = 0; hf < 2; hf++) {
                int c = nh * 128 + ng * 16 + hf * 8 + tg * 2;
                float* dd = d[2 * ng + hf];
                p1 = fmaf(silu_fast(dd[0] + s.vbc1[c]), s.vwc2[c], p1);
                p1 = fmaf(silu_fast(dd[1] + s.vbc1[c + 1]), s.vwc2[c + 1], p1);
                p2 = fmaf(silu_fast(dd[2] + s.vbc1[c]), s.vwc2[c], p2);
                p2 = fmaf(silu_fast(dd[3] + s.vbc1[c + 1]), s.vwc2[c + 1], p2);
            }
        }
        p1 += __shfl_xor_sync(0xFFFFFFFF, p1, 1);
        p1 += __shfl_xor_sync(0xFFFFFFFF, p1, 2);
        p2 += __shfl_xor_sync(0xFFFFFFFF, p2, 1);
        p2 += __shfl_xor_sync(0xFFFFFFFF, p2, 2);
        if (tg == 0) {
            s.P[rr1 * 2 + nh] = p1;
            s.P[rr2 * 2 + nh] = p2;
        }
    }
    __syncthreads();

    // coord atomics
    if (tid < 128) {
        float scal = s.P[tid * 2] + s.P[tid * 2 + 1] + __ldg(bc2);
        int ri = s.rowI[tid];
        atomicAdd(&g_aggC[ri * 3 + 0], s.cd[tid * 3 + 0] * scal);
        atomicAdd(&g_aggC[ri * 3 + 1], s.cd[tid * 3 + 1] * scal);
        atomicAdd(&g_aggC[ri * 3 + 2], s.cd[tid * 3 + 2] * scal);
        atomicAdd(&g_cnt[ri], 1.0f);
    }
}

// ---------------- node kernel ----------------
struct __align__(16) NSm { float X[64 * 260]; float B[32 * 256]; float A[64 * 33]; };

__global__ __launch_bounds__(256, 2) void node_kernel(
    const float* __restrict__ h, const float* __restrict__ coord,
    const float* __restrict__ Wn1, const float* __restrict__ bn1,
    const float* __restrict__ Wn2, const float* __restrict__ bn2,
    float* __restrict__ out) {
    extern __shared__ char smem_raw[];
    NSm& s = *reinterpret_cast<NSm*>(smem_raw);
    const int tid = threadIdx.x, tx = tid & 15, ty = tid >> 4, r0 = ty * 4;
    const int nb = blockIdx.x * 64;
    ull acc[4][8];
#pragma unroll
    for (int r = 0; r < 4; r++)
#pragma unroll
        for (int j = 0; j < 8; j++) acc[r][j] = 0ULL;
    const int rr = tid >> 2, kk = (tid & 3) * 8;
    const int nrow = nb + rr;
    const bool vA = nrow < Nn;

    for (int kc = 0; kc < 16; kc++) {
        const int kb = kc * 32;
        float4 v0 = make_float4(0.f, 0.f, 0.f, 0.f), v1 = v0;
        if (vA) {
            const float* src = (kc < 8) ? h + (size_t)nrow * 256 + kb + kk
                                        : g_aggH + (size_t)nrow * 256 + (kb - 256) + kk;
            v0 = *reinterpret_cast<const float4*>(src);
            v1 = *reinterpret_cast<const float4*>(src + 4);
        }
        float* da = &s.A[rr * 33 + kk];
        da[0] = v0.x; da[1] = v0.y; da[2] = v0.z; da[3] = v0.w;
        da[4] = v1.x; da[5] = v1.y; da[6] = v1.z; da[7] = v1.w;
        const float4* wsrc = reinterpret_cast<const float4*>(Wn1 + (size_t)kb * 256);
        float4* wdst = reinterpret_cast<float4*>(s.B);
#pragma unroll
        for (int i = 0; i < 8; i++) wdst[tid + 256 * i] = wsrc[tid + 256 * i];
        __syncthreads();
        mma_chunk<33>(&s.A[0], s.B, acc, tx, r0);
        __syncthreads();
    }
#pragma unroll
    for (int r = 0; r < 4; r++)
#pragma unroll
        for (int jj = 0; jj < 4; jj++) {
            int c0 = 4 * tx + 64 * jj;
            float2 p0 = unpack2(acc[r][2 * jj]), p1 = unpack2(acc[r][2 * jj + 1]);
            float4 o;
            o.x = silu_fast(p0.x + __ldg(&bn1[c0 + 0]));
            o.y = silu_fast(p0.y + __ldg(&bn1[c0 + 1]));
            o.z = silu_fast(p1.x + __ldg(&bn1[c0 + 2]));
            o.w = silu_fast(p1.y + __ldg(&bn1[c0 + 3]));
            *reinterpret_cast<float4*>(&s.X[(r0 + r) * 260 + c0]) = o;
            acc[r][2 * jj] = 0ULL; acc[r][2 * jj + 1] = 0ULL;
        }
    __syncthreads();
    for (int kc = 0; kc < 8; kc++) {
        const int kb = kc * 32;
        const float4* wsrc = reinterpret_cast<const float4*>(Wn2 + (size_t)kb * 256);
        float4* wdst = reinterpret_cast<float4*>(s.B);
#pragma unroll
        for (int i = 0; i < 8; i++) wdst[tid + 256 * i] = wsrc[tid + 256 * i];
        __syncthreads();
        mma_chunk<260>(&s.X[kb], s.B, acc, tx, r0);
        __syncthreads();
    }
#pragma unroll
    for (int r = 0; r < 4; r++) {
        int n = nb + r0 + r;
        if (n < Nn) {
#pragma unroll
            for (int jj = 0; jj < 4; jj++) {
                int c0 = 4 * tx + 64 * jj;
                float2 p0 = unpack2(acc[r][2 * jj]), p1 = unpack2(acc[r][2 * jj + 1]);
                float4 o;
                o.x = p0.x + __ldg(&bn2[c0 + 0]); o.y = p0.y + __ldg(&bn2[c0 + 1]);
                o.z = p1.x + __ldg(&bn2[c0 + 2]); o.w = p1.y + __ldg(&bn2[c0 + 3]);
                *reinterpret_cast<float4*>(&out[(size_t)n * 256 + c0]) = o;
            }
        }
    }
    if (tid < 64) {
        int n = nb + tid;
        if (n < Nn) {
            float inv = 1.0f / fmaxf(g_cnt[n], 1.0f);
#pragma unroll
            for (int dd = 0; dd < 3; dd++)
                out[(size_t)Nn * 256 + n * 3 + dd] = coord[n * 3 + dd] + g_aggC[n * 3 + dd] * inv;
        }
    }
}

// ---------------------------------------------------------------------------
extern "C" void kernel_launch(void* const* d_in, const int* in_sizes, int n_in,
                              void* d_out, int out_size) {
    const float* h     = (const float*)d_in[0];
    const float* coord = (const float*)d_in[1];
    const int*   ei    = (const int*)d_in[2];
    const float* We1   = (const float*)d_in[3];
    const float* be1   = (const float*)d_in[4];
    const float* We2   = (const float*)d_in[5];
    const float* be2   = (const float*)d_in[6];
    const float* Wn1   = (const float*)d_in[7];
    const float* bn1   = (const float*)d_in[8];
    const float* Wn2   = (const float*)d_in[9];
    const float* bn2   = (const float*)d_in[10];
    const float* Wc1   = (const float*)d_in[11];
    const float* bc1   = (const float*)d_in[12];
    const float* Wc2   = (const float*)d_in[13];
    const float* bc2   = (const float*)d_in[14];
    float* out = (float*)d_out;

    cudaFuncSetAttribute(edge_kernel, cudaFuncAttributeMaxDynamicSharedMemorySize, (int)sizeof(ESm));
    cudaFuncSetAttribute(node_kernel, cudaFuncAttributeMaxDynamicSharedMemorySize, (int)sizeof(NSm));
    cudaFuncSetAttribute(pcomp_kernel, cudaFuncAttributeMaxDynamicSharedMemorySize, (int)sizeof(PSm));

    zero_kernel<<<1280, 256>>>();
    prep_w<<<256, 256>>>(We2, 1);
    prep_w<<<256, 256>>>(Wc1, 2);
    pcomp_kernel<<<dim3((Nn + 63) / 64, 2), 256, sizeof(PSm)>>>(h, We1);
    edge_kernel<<<Ee / 128, 512, sizeof(ESm)>>>(coord, ei, We1, be1, be2, bc1, Wc2, bc2);
    node_kernel<<<(Nn + 63) / 64, 256, sizeof(NSm)>>>(h, coord, Wn1, bn1, Wn2, bn2, out);
}